// round 1
// baseline (speedup 1.0000x reference)
#include <cuda_runtime.h>
#include <math.h>

// Problem constants
constexpr int NB   = 16384;   // batch
constexpr int NF   = 18;      // features
constexpr int NE   = 64;      // embedding dim
constexpr int IN0  = 1152;    // NF*NE
constexpr int D1   = 512;
constexpr int D2   = 256;
constexpr int NVOC = 100000;

// ---------------- static device scratch (no allocs allowed) ----------------
__device__ float d_feat [(size_t)NB*IN0];        // gathered embeddings
__device__ float d_h0   [(size_t)12*NB*D1];      // layer0 expert outputs [e][b][o]
__device__ float d_h1   [(size_t)16*NB*D2];      // layer1 stream-expert outputs [s][b][o]
__device__ float d_fea1 [(size_t)2*NB*D1];       // layer0 combined per-task [t][b][o]
__device__ float d_fea2 [(size_t)2*NB*D2];       // layer1 combined per-task
__device__ float d_t1raw[(size_t)2*NB*128];
__device__ float d_t1   [(size_t)2*NB*128];
__device__ float d_t2raw[(size_t)2*NB*64];
__device__ float d_t2   [(size_t)2*NB*64];
__device__ float d_gate0[(size_t)NB*16];
__device__ float d_gate1[(size_t)NB*16];

// BN batch-stat accumulators + folded affine (y = h*a + c)
__device__ float d_sum0[12*D1], d_sq0[12*D1], d_a0[12*D1], d_c0[12*D1];
__device__ float d_sum1[16*D2], d_sq1[16*D2], d_a1[16*D2], d_c1[16*D2];
__device__ float d_sumT0[2*128], d_sqT0[2*128], d_aT0[2*128], d_cT0[2*128];
__device__ float d_sumT1[2*64],  d_sqT1[2*64],  d_aT1[2*64],  d_cT1[2*64];

// stream-expert (s = t*8 + k) -> real expert index.
// TASK_IDX[0] = {0,1,2,3,8,9,10,11}, TASK_IDX[1] = {4,5,6,7,8,9,10,11}
__device__ __forceinline__ int expert_of(int z){
  int t = z >> 3, k = z & 7;
  return (k < 4) ? (t*4 + k) : (4 + k);
}

// ---------------- kernels ----------------

__global__ void zero_stats_kernel(){
  int i = blockIdx.x*blockDim.x + threadIdx.x;
  if(i < 12*D1){ d_sum0[i]=0.f; d_sq0[i]=0.f; }
  if(i < 16*D2){ d_sum1[i]=0.f; d_sq1[i]=0.f; }
  if(i < 2*128){ d_sumT0[i]=0.f; d_sqT0[i]=0.f; }
  if(i < 2*64 ){ d_sumT1[i]=0.f; d_sqT1[i]=0.f; }
}

__global__ void gather_kernel(const int* __restrict__ x, const float* __restrict__ emb){
  int idx = blockIdx.x*blockDim.x + threadIdx.x;   // NB*NF*NE threads
  int e = idx & (NE-1);
  int f = (idx >> 6) % NF;
  int b = idx / (NE*NF);
  int v = x[b*NF + f];
  d_feat[(size_t)b*IN0 + f*NE + e] = emb[((size_t)f*NVOC + (size_t)v)*NE + e];
}

__device__ __forceinline__ void warp_reduce16(float* acc){
  #pragma unroll
  for(int off=16; off; off>>=1)
    #pragma unroll
    for(int j=0;j<16;j++) acc[j] += __shfl_xor_sync(0xffffffffu, acc[j], off);
}

__device__ __forceinline__ void softmax8(const float* l, float* o){
  float m = l[0];
  #pragma unroll
  for(int j=1;j<8;j++) m = fmaxf(m, l[j]);
  float s = 0.f, e[8];
  #pragma unroll
  for(int j=0;j<8;j++){ e[j] = expf(l[j]-m); s += e[j]; }
  float inv = 1.f/s;
  #pragma unroll
  for(int j=0;j<8;j++) o[j] = e[j]*inv;
}

// gate logits for both tasks at layer 0: feat @ gw0[t] + gb0[t], softmax over 8
__global__ void gate0_kernel(const float* __restrict__ gw, const float* __restrict__ gb){
  int w = (blockIdx.x*blockDim.x + threadIdx.x) >> 5;
  int lane = threadIdx.x & 31;
  if(w >= NB) return;
  const float* frow = d_feat + (size_t)w*IN0;
  float acc[16];
  #pragma unroll
  for(int j=0;j<16;j++) acc[j]=0.f;
  for(int k=lane;k<IN0;k+=32){
    float fv = frow[k];
    const float* g0 = gw + k*8;            // gw0[0]
    const float* g1 = gw + IN0*8 + k*8;    // gw0[1]
    #pragma unroll
    for(int j=0;j<8;j++){ acc[j] += fv*g0[j]; acc[8+j] += fv*g1[j]; }
  }
  warp_reduce16(acc);
  if(lane==0){
    float l[8], o[8];
    #pragma unroll
    for(int t=0;t<2;t++){
      #pragma unroll
      for(int j=0;j<8;j++) l[j] = acc[t*8+j] + gb[t*8+j];
      softmax8(l,o);
      #pragma unroll
      for(int j=0;j<8;j++) d_gate0[(size_t)w*16 + t*8 + j] = o[j];
    }
  }
}

__global__ void gate1_kernel(const float* __restrict__ gw, const float* __restrict__ gb){
  int w = (blockIdx.x*blockDim.x + threadIdx.x) >> 5;
  int lane = threadIdx.x & 31;
  if(w >= NB) return;
  const float* f0 = d_fea1 + (size_t)w*D1;
  const float* f1 = d_fea1 + (size_t)NB*D1 + (size_t)w*D1;
  float acc[16];
  #pragma unroll
  for(int j=0;j<16;j++) acc[j]=0.f;
  for(int k=lane;k<D1;k+=32){
    float v0 = f0[k], v1 = f1[k];
    const float* g0 = gw + k*8;
    const float* g1 = gw + D1*8 + k*8;
    #pragma unroll
    for(int j=0;j<8;j++){ acc[j] += v0*g0[j]; acc[8+j] += v1*g1[j]; }
  }
  warp_reduce16(acc);
  if(lane==0){
    float l[8], o[8];
    #pragma unroll
    for(int t=0;t<2;t++){
      #pragma unroll
      for(int j=0;j<8;j++) l[j] = acc[t*8+j] + gb[t*8+j];
      softmax8(l,o);
      #pragma unroll
      for(int j=0;j<8;j++) d_gate1[(size_t)w*16 + t*8 + j] = o[j];
    }
  }
}

// Generic batched SGEMM C[z] = A[z] @ W[z], 128x128x8 tiles, 8x8 per thread.
// Epilogue accumulates per-output-column sum & sumsq (for BatchNorm batch stats).
// mode 0: layer0 experts; 1: layer1 stream-experts; 2: tower layer0; 3: tower layer1.
__global__ void __launch_bounds__(256,2) sgemm_kernel(int mode, const float* __restrict__ w_base){
  __shared__ float sh[2048];              // As = sh[0:1024], Bs = sh[1024:2048]
  float* As = sh;
  float* Bs = sh + 1024;

  const int z = blockIdx.z;
  const float* A; const float* W; float* C; float* sumP; float* sqP;
  int N, K;
  if(mode==0){
    A=d_feat; K=IN0; N=D1;
    W=w_base + (size_t)z*K*N; C=d_h0 + (size_t)z*NB*N;
    sumP=d_sum0 + z*N; sqP=d_sq0 + z*N;
  } else if(mode==1){
    int t = z >> 3; int e = expert_of(z);
    A=d_fea1 + (size_t)t*NB*D1; K=D1; N=D2;
    W=w_base + (size_t)e*K*N; C=d_h1 + (size_t)z*NB*N;
    sumP=d_sum1 + z*N; sqP=d_sq1 + z*N;
  } else if(mode==2){
    A=d_fea2 + (size_t)z*NB*D2; K=D2; N=128;
    W=w_base + (size_t)z*K*N; C=d_t1raw + (size_t)z*NB*N;
    sumP=d_sumT0 + z*N; sqP=d_sqT0 + z*N;
  } else {
    A=d_t1 + (size_t)z*NB*128; K=128; N=64;
    W=w_base + (size_t)z*K*N; C=d_t2raw + (size_t)z*NB*N;
    sumP=d_sumT1 + z*N; sqP=d_sqT1 + z*N;
  }

  const int tid = threadIdx.x;
  const int tx = tid & 15, ty = tid >> 4;
  const int m0 = blockIdx.y*128, n0 = blockIdx.x*128;
  const int arow = tid >> 1, acol = (tid & 1)*4;
  const int brow = tid >> 5, bcol = (tid & 31)*4;

  float acc[8][8];
  #pragma unroll
  for(int i=0;i<8;i++)
    #pragma unroll
    for(int j=0;j<8;j++) acc[i][j]=0.f;

  const float* Aptr = A + (size_t)(m0+arow)*K + acol;
  const bool bload = (n0 + bcol) < N;

  for(int k0=0; k0<K; k0+=8){
    float4 av = *(const float4*)(Aptr + k0);
    As[(acol+0)*128 + arow] = av.x;
    As[(acol+1)*128 + arow] = av.y;
    As[(acol+2)*128 + arow] = av.z;
    As[(acol+3)*128 + arow] = av.w;
    float4 bv = bload ? *(const float4*)(W + (size_t)(k0+brow)*N + n0 + bcol)
                      : make_float4(0.f,0.f,0.f,0.f);
    *(float4*)(Bs + brow*128 + bcol) = bv;
    __syncthreads();
    #pragma unroll
    for(int kk=0;kk<8;kk++){
      float a[8], bb[8];
      *(float4*)(a)    = *(float4*)(As + kk*128 + ty*8);
      *(float4*)(a+4)  = *(float4*)(As + kk*128 + ty*8 + 4);
      *(float4*)(bb)   = *(float4*)(Bs + kk*128 + tx*8);
      *(float4*)(bb+4) = *(float4*)(Bs + kk*128 + tx*8 + 4);
      #pragma unroll
      for(int i=0;i<8;i++)
        #pragma unroll
        for(int j=0;j<8;j++) acc[i][j] += a[i]*bb[j];
    }
    __syncthreads();
  }

  // store + per-column partial stats
  float s1[8], s2[8];
  #pragma unroll
  for(int j=0;j<8;j++){ s1[j]=0.f; s2[j]=0.f; }
  const bool wok = (n0 + tx*8) < N;
  #pragma unroll
  for(int i=0;i<8;i++){
    int m = m0 + ty*8 + i;
    #pragma unroll
    for(int j=0;j<8;j++){ float v = acc[i][j]; s1[j]+=v; s2[j]+=v*v; }
    if(wok){
      *(float4*)(C + (size_t)m*N + n0 + tx*8)     = *(float4*)&acc[i][0];
      *(float4*)(C + (size_t)m*N + n0 + tx*8 + 4) = *(float4*)&acc[i][4];
    }
  }
  // reduce across ty (16 threads per column group) via smem, then atomics
  __syncthreads();
  #pragma unroll
  for(int j=0;j<8;j++) sh[ty*128 + tx*8 + j] = s1[j];
  __syncthreads();
  if(tid < 128 && (n0 + tid) < N){
    float t = 0.f;
    #pragma unroll
    for(int r=0;r<16;r++) t += sh[r*128 + tid];
    atomicAdd(&sumP[n0 + tid], t);
  }
  __syncthreads();
  #pragma unroll
  for(int j=0;j<8;j++) sh[ty*128 + tx*8 + j] = s2[j];
  __syncthreads();
  if(tid < 128 && (n0 + tid) < N){
    float t = 0.f;
    #pragma unroll
    for(int r=0;r<16;r++) t += sh[r*128 + tid];
    atomicAdd(&sqP[n0 + tid], t);
  }
}

// fold batch stats into y = h*a + c  (bias before BN cancels; gamma/beta applied)
__global__ void finalize_kernel(int mode, const float* __restrict__ g, const float* __restrict__ bt){
  int i = blockIdx.x*blockDim.x + threadIdx.x;
  const float* sum; const float* sq; float* a; float* c; int N, NZ;
  if(mode==0){ sum=d_sum0; sq=d_sq0; a=d_a0; c=d_c0; N=D1; NZ=12; }
  else if(mode==1){ sum=d_sum1; sq=d_sq1; a=d_a1; c=d_c1; N=D2; NZ=16; }
  else if(mode==2){ sum=d_sumT0; sq=d_sqT0; a=d_aT0; c=d_cT0; N=128; NZ=2; }
  else { sum=d_sumT1; sq=d_sqT1; a=d_aT1; c=d_cT1; N=64; NZ=2; }
  if(i >= NZ*N) return;
  int z = i / N, o = i - z*N;
  int gz = (mode==1) ? expert_of(z) : z;
  float mu  = sum[i] * (1.f/NB);
  float var = sq[i] * (1.f/NB) - mu*mu;
  float aa  = g[gz*N+o] * rsqrtf(var + 1e-5f);
  a[i] = aa;
  c[i] = bt[gz*N+o] - mu*aa;
}

// layer-0: BN+relu per expert, gate-weighted sum over 8 experts per task.
// Each expert's h is read exactly once (shared experts feed both tasks).
__global__ void combine0_kernel(){
  int idx = blockIdx.x*blockDim.x + threadIdx.x;   // NB*D1
  int o = idx & (D1-1);
  size_t b = (size_t)(idx >> 9);
  const float* g = d_gate0 + b*16;
  float acc0 = 0.f, acc1 = 0.f;
  #pragma unroll
  for(int e=0;e<12;e++){
    float h = d_h0[((size_t)e*NB + b)*D1 + o];
    float y = fmaxf(h*d_a0[e*D1+o] + d_c0[e*D1+o], 0.f);
    if(e < 4)       acc0 += g[e]*y;                       // task0 specific
    else if(e < 8)  acc1 += g[8 + e - 4]*y;               // task1 specific
    else { acc0 += g[e-4]*y; acc1 += g[8 + e - 4]*y; }    // shared experts
  }
  d_fea1[b*D1 + o] = acc0;
  d_fea1[(size_t)NB*D1 + b*D1 + o] = acc1;
}

__global__ void combine1_kernel(){
  int idx = blockIdx.x*blockDim.x + threadIdx.x;   // NB*D2
  int o = idx & (D2-1);
  size_t b = (size_t)(idx >> 8);
  const float* g = d_gate1 + b*16;
  float acc0 = 0.f, acc1 = 0.f;
  #pragma unroll
  for(int s=0;s<16;s++){
    float h = d_h1[((size_t)s*NB + b)*D2 + o];
    float y = fmaxf(h*d_a1[s*D2+o] + d_c1[s*D2+o], 0.f);
    if(s < 8) acc0 += g[s]*y; else acc1 += g[s]*y;
  }
  d_fea2[b*D2 + o] = acc0;
  d_fea2[(size_t)NB*D2 + b*D2 + o] = acc1;
}

__global__ void normrelu_kernel(int mode){
  int i = blockIdx.x*blockDim.x + threadIdx.x;
  if(mode==0){
    if(i >= 2*NB*128) return;
    int o = i & 127; int t = i / (NB*128);
    d_t1[i] = fmaxf(d_t1raw[i]*d_aT0[t*128+o] + d_cT0[t*128+o], 0.f);
  } else {
    if(i >= 2*NB*64) return;
    int o = i & 63; int t = i / (NB*64);
    d_t2[i] = fmaxf(d_t2raw[i]*d_aT1[t*64+o] + d_cT1[t*64+o], 0.f);
  }
}

__global__ void final_kernel(const float* __restrict__ tow, const float* __restrict__ tob,
                             float* __restrict__ out){
  int w = (blockIdx.x*blockDim.x + threadIdx.x) >> 5;
  int lane = threadIdx.x & 31;
  if(w >= NB) return;
  size_t b = (size_t)w;
  float s0 = d_t2[b*64 + lane]*tow[lane] + d_t2[b*64 + lane + 32]*tow[lane + 32];
  float s1 = d_t2[(size_t)NB*64 + b*64 + lane]*tow[64 + lane]
           + d_t2[(size_t)NB*64 + b*64 + lane + 32]*tow[64 + lane + 32];
  #pragma unroll
  for(int off=16; off; off>>=1){
    s0 += __shfl_xor_sync(0xffffffffu, s0, off);
    s1 += __shfl_xor_sync(0xffffffffu, s1, off);
  }
  if(lane==0){
    out[b]      = 1.f/(1.f + expf(-(s0 + tob[0])));
    out[NB + b] = 1.f/(1.f + expf(-(s1 + tob[1])));
  }
}

// ---------------- host launcher ----------------
extern "C" void kernel_launch(void* const* d_in, const int* in_sizes, int n_in,
                              void* d_out, int out_size){
  const int*   x    = (const int*)  d_in[0];
  const float* emb  = (const float*)d_in[1];
  const float* ew0  = (const float*)d_in[2];
  // d_in[3] = eb0  (bias cancels under BatchNorm)
  const float* eg0  = (const float*)d_in[4];
  const float* ebt0 = (const float*)d_in[5];
  const float* gw0  = (const float*)d_in[6];
  const float* gb0  = (const float*)d_in[7];
  // d_in[8..9] = gsw0, gsb0 (shared stream pruned)
  const float* ew1  = (const float*)d_in[10];
  const float* eg1  = (const float*)d_in[12];
  const float* ebt1 = (const float*)d_in[13];
  const float* gw1  = (const float*)d_in[14];
  const float* gb1  = (const float*)d_in[15];
  const float* tw0  = (const float*)d_in[18];
  const float* tg0  = (const float*)d_in[20];
  const float* tbt0 = (const float*)d_in[21];
  const float* tw1  = (const float*)d_in[22];
  const float* tg1  = (const float*)d_in[24];
  const float* tbt1 = (const float*)d_in[25];
  const float* tow  = (const float*)d_in[26];
  const float* tob  = (const float*)d_in[27];
  float* out = (float*)d_out;

  zero_stats_kernel<<<(12*D1 + 255)/256, 256>>>();
  gather_kernel<<<(NB*NF*NE)/256, 256>>>(x, emb);
  gate0_kernel<<<(NB*32)/256, 256>>>(gw0, gb0);

  sgemm_kernel<<<dim3(D1/128, NB/128, 12), 256>>>(0, ew0);
  finalize_kernel<<<(12*D1 + 255)/256, 256>>>(0, eg0, ebt0);
  combine0_kernel<<<(NB*D1)/256, 256>>>();

  gate1_kernel<<<(NB*32)/256, 256>>>(gw1, gb1);
  sgemm_kernel<<<dim3(D2/128, NB/128, 16), 256>>>(1, ew1);
  finalize_kernel<<<(16*D2 + 255)/256, 256>>>(1, eg1, ebt1);
  combine1_kernel<<<(NB*D2)/256, 256>>>();

  sgemm_kernel<<<dim3(1, NB/128, 2), 256>>>(2, tw0);
  finalize_kernel<<<1, 256>>>(2, tg0, tbt0);
  normrelu_kernel<<<(2*NB*128)/256, 256>>>(0);

  sgemm_kernel<<<dim3(1, NB/128, 2), 256>>>(3, tw1);
  finalize_kernel<<<1, 256>>>(3, tg1, tbt1);
  normrelu_kernel<<<(2*NB*64)/256, 256>>>(1);

  final_kernel<<<(NB*32)/256, 256>>>(tow, tob, out);
}

// round 3
// speedup vs baseline: 1.6228x; 1.6228x over previous
#include <cuda_runtime.h>
#include <mma.h>
#include <math.h>
#include <stdint.h>

using namespace nvcuda;

// Problem constants
constexpr int NB   = 16384;
constexpr int NF   = 18;
constexpr int NE   = 64;
constexpr int IN0  = 1152;
constexpr int D1   = 512;
constexpr int D2   = 256;
constexpr int NVOC = 100000;

// ---------------- static device scratch ----------------
__device__ __align__(1024) float d_feat [(size_t)NB*IN0];
__device__ __align__(1024) float d_h0   [(size_t)12*NB*D1];
__device__ __align__(1024) float d_h1   [(size_t)16*NB*D2];
__device__ __align__(1024) float d_fea1 [(size_t)2*NB*D1];
__device__ __align__(1024) float d_fea2 [(size_t)2*NB*D2];
__device__ float d_t1raw[(size_t)2*NB*128];
__device__ float d_t1   [(size_t)2*NB*128];
__device__ float d_t2raw[(size_t)2*NB*64];
__device__ float d_t2   [(size_t)2*NB*64];
__device__ float d_gate0[(size_t)NB*16];
__device__ float d_gate1[(size_t)NB*16];

__device__ float d_sum0[12*D1], d_sq0[12*D1], d_a0[12*D1], d_c0[12*D1];
__device__ float d_sum1[16*D2], d_sq1[16*D2], d_a1[16*D2], d_c1[16*D2];
__device__ float d_sumT0[2*128], d_sqT0[2*128], d_aT0[2*128], d_cT0[2*128];
__device__ float d_sumT1[2*64],  d_sqT1[2*64],  d_aT1[2*64],  d_cT1[2*64];

__device__ __forceinline__ int expert_of(int z){
  int t = z >> 3, k = z & 7;
  return (k < 4) ? (t*4 + k) : (4 + k);
}

// ---------------- cp.async helpers (sm_80 baseline; safe on compute_103) ----
__device__ __forceinline__ uint32_t smem_u32(const void* p){
  uint32_t a;
  asm("{ .reg .u64 t; cvta.to.shared.u64 t, %1; cvt.u32.u64 %0, t; }" : "=r"(a) : "l"(p));
  return a;
}
__device__ __forceinline__ void cp16(uint32_t s, const void* g){
  asm volatile("cp.async.cg.shared.global [%0], [%1], 16;" :: "r"(s), "l"(g) : "memory");
}
#define CP_COMMIT() asm volatile("cp.async.commit_group;" ::: "memory")
#define CP_WAIT(n)  asm volatile("cp.async.wait_group %0;" :: "n"(n) : "memory")

// ---------------- wmma tf32 grouped GEMM ----------------
// C[z][M,N] = A[z][M,K] @ W[z][K,N], A row-major, W row-major.
// CTA tile 128x128, BK=32, double-buffered cp.async, 8 warps (each 64x32).
constexpr int BM = 128, BN = 128, BK = 32;
constexpr int A_LD = 36;                 // 32 + 4 pad floats
constexpr int B_LD = 132;                // 128 + 4 pad floats
constexpr int A_STAGE = BM * A_LD;       // 4608 floats
constexpr int B_STAGE = BK * B_LD;       // 4224 floats
constexpr int SMEM_GEMM_FLOATS = 2*A_STAGE + 2*B_STAGE;   // 17664
constexpr int SMEM_GEMM_BYTES  = SMEM_GEMM_FLOATS * 4;    // 70656

typedef wmma::fragment<wmma::matrix_a, 16,16,8, wmma::precision::tf32, wmma::row_major> FragA;
typedef wmma::fragment<wmma::matrix_b, 16,16,8, wmma::precision::tf32, wmma::row_major> FragB;
typedef wmma::fragment<wmma::accumulator, 16,16,8, float> FragC;

__global__ void __launch_bounds__(256) wmma_gemm_kernel(int mode, const float* __restrict__ w_base){
  extern __shared__ float sh[];
  const uint32_t sb = smem_u32(sh);
  const int tid = threadIdx.x;
  const int wid = tid >> 5;
  const int wm = wid >> 2;     // 0..1 -> 64-row slice
  const int wn = wid & 3;      // 0..3 -> 32-col slice

  const int z = blockIdx.z;
  const float* A; const float* W; float* C;
  int N, K;
  if(mode == 0){
    A = d_feat; K = IN0; N = D1;
    W = w_base + (size_t)z*K*N;
    C = d_h0 + (size_t)z*NB*N;
  } else {
    int t = z >> 3, e = expert_of(z);
    A = d_fea1 + (size_t)t*NB*D1; K = D1; N = D2;
    W = w_base + (size_t)e*K*N;
    C = d_h1 + (size_t)z*NB*N;
  }
  const int NK = K / BK;
  const int m0 = blockIdx.y * BM;
  const int n0 = blockIdx.x * BN;

  const float* Abase = A + (size_t)m0 * K;
  const float* Bbase = W + n0;

  // async copy of one stage
  auto load_stage = [&](int kc, int buf){
    const float* gA = Abase + (size_t)kc * BK;
    const float* gB = Bbase + (size_t)kc * BK * N;
    uint32_t sA = sb + buf * (A_STAGE*4);
    uint32_t sB = sb + 2*(A_STAGE*4) + buf * (B_STAGE*4);
    // A: 128 rows x 8 float4
    #pragma unroll
    for(int it = 0; it < 4; ++it){
      int idx = it*256 + tid;
      int r = idx >> 3, q = idx & 7;
      cp16(sA + (uint32_t)(r*A_LD + q*4)*4, gA + (size_t)r*K + q*4);
    }
    // B: 32 rows x 32 float4
    #pragma unroll
    for(int it = 0; it < 4; ++it){
      int idx = it*256 + tid;
      int r = idx >> 5, q = idx & 31;
      cp16(sB + (uint32_t)(r*B_LD + q*4)*4, gB + (size_t)r*N + q*4);
    }
  };

  FragC acc[4][2];
  #pragma unroll
  for(int i = 0; i < 4; ++i)
    #pragma unroll
    for(int j = 0; j < 2; ++j) wmma::fill_fragment(acc[i][j], 0.f);

  load_stage(0, 0);
  CP_COMMIT();

  for(int kc = 0; kc < NK; ++kc){
    if(kc + 1 < NK){
      load_stage(kc+1, (kc+1) & 1);
      CP_COMMIT();
      CP_WAIT(1);
    } else {
      CP_WAIT(0);
    }
    __syncthreads();
    const float* As = sh + (kc & 1) * A_STAGE;
    const float* Bs = sh + 2*A_STAGE + (kc & 1) * B_STAGE;
    #pragma unroll
    for(int ks = 0; ks < 4; ++ks){
      FragA a[4];
      FragB b[2];
      #pragma unroll
      for(int im = 0; im < 4; ++im){
        wmma::load_matrix_sync(a[im], As + (wm*64 + im*16)*A_LD + ks*8, A_LD);
        #pragma unroll
        for(int t = 0; t < a[im].num_elements; ++t)
          a[im].x[t] = wmma::__float_to_tf32(a[im].x[t]);
      }
      #pragma unroll
      for(int jn = 0; jn < 2; ++jn){
        wmma::load_matrix_sync(b[jn], Bs + (ks*8)*B_LD + wn*32 + jn*16, B_LD);
        #pragma unroll
        for(int t = 0; t < b[jn].num_elements; ++t)
          b[jn].x[t] = wmma::__float_to_tf32(b[jn].x[t]);
      }
      #pragma unroll
      for(int im = 0; im < 4; ++im)
        #pragma unroll
        for(int jn = 0; jn < 2; ++jn)
          wmma::mma_sync(acc[im][jn], a[im], b[jn], acc[im][jn]);
    }
    __syncthreads();
  }

  #pragma unroll
  for(int im = 0; im < 4; ++im)
    #pragma unroll
    for(int jn = 0; jn < 2; ++jn)
      wmma::store_matrix_sync(C + (size_t)(m0 + wm*64 + im*16)*N + (n0 + wn*32 + jn*16),
                              acc[im][jn], N, wmma::mem_row_major);
}

// ---------------- BN column stats over h (sum / sumsq) ----------------
__global__ void colsum_kernel(int mode){
  int z = blockIdx.z;
  const float* H; float* sum; float* sq; int N;
  if(mode == 0){ H = d_h0 + (size_t)z*NB*D1; sum = d_sum0 + z*D1; sq = d_sq0 + z*D1; N = D1; }
  else         { H = d_h1 + (size_t)z*NB*D2; sum = d_sum1 + z*D2; sq = d_sq1 + z*D2; N = D2; }
  int col = blockIdx.x*256 + threadIdx.x;
  const float* p = H + (size_t)blockIdx.y*256*N + col;
  float s = 0.f, q = 0.f;
  #pragma unroll 8
  for(int r = 0; r < 256; ++r){ float v = p[(size_t)r*N]; s += v; q += v*v; }
  atomicAdd(&sum[col], s);
  atomicAdd(&sq[col], q);
}

// ---------------- small kernels ----------------
__global__ void zero_stats_kernel(){
  int i = blockIdx.x*blockDim.x + threadIdx.x;
  if(i < 12*D1){ d_sum0[i]=0.f; d_sq0[i]=0.f; }
  if(i < 16*D2){ d_sum1[i]=0.f; d_sq1[i]=0.f; }
  if(i < 2*128){ d_sumT0[i]=0.f; d_sqT0[i]=0.f; }
  if(i < 2*64 ){ d_sumT1[i]=0.f; d_sqT1[i]=0.f; }
}

__global__ void gather_kernel(const int* __restrict__ x, const float* __restrict__ emb){
  int idx = blockIdx.x*blockDim.x + threadIdx.x;
  int e = idx & (NE-1);
  int f = (idx >> 6) % NF;
  int b = idx / (NE*NF);
  int v = x[b*NF + f];
  d_feat[(size_t)b*IN0 + f*NE + e] = emb[((size_t)f*NVOC + (size_t)v)*NE + e];
}

__device__ __forceinline__ void warp_reduce16(float* acc){
  #pragma unroll
  for(int off=16; off; off>>=1)
    #pragma unroll
    for(int j=0;j<16;j++) acc[j] += __shfl_xor_sync(0xffffffffu, acc[j], off);
}
__device__ __forceinline__ void softmax8(const float* l, float* o){
  float m = l[0];
  #pragma unroll
  for(int j=1;j<8;j++) m = fmaxf(m, l[j]);
  float s = 0.f, e[8];
  #pragma unroll
  for(int j=0;j<8;j++){ e[j] = expf(l[j]-m); s += e[j]; }
  float inv = 1.f/s;
  #pragma unroll
  for(int j=0;j<8;j++) o[j] = e[j]*inv;
}

__global__ void gate0_kernel(const float* __restrict__ gw, const float* __restrict__ gb){
  int w = (blockIdx.x*blockDim.x + threadIdx.x) >> 5;
  int lane = threadIdx.x & 31;
  if(w >= NB) return;
  const float* frow = d_feat + (size_t)w*IN0;
  float acc[16];
  #pragma unroll
  for(int j=0;j<16;j++) acc[j]=0.f;
  for(int k=lane;k<IN0;k+=32){
    float fv = frow[k];
    const float* g0 = gw + k*8;
    const float* g1 = gw + IN0*8 + k*8;
    #pragma unroll
    for(int j=0;j<8;j++){ acc[j] += fv*g0[j]; acc[8+j] += fv*g1[j]; }
  }
  warp_reduce16(acc);
  if(lane==0){
    float l[8], o[8];
    #pragma unroll
    for(int t=0;t<2;t++){
      #pragma unroll
      for(int j=0;j<8;j++) l[j] = acc[t*8+j] + gb[t*8+j];
      softmax8(l,o);
      #pragma unroll
      for(int j=0;j<8;j++) d_gate0[(size_t)w*16 + t*8 + j] = o[j];
    }
  }
}

__global__ void gate1_kernel(const float* __restrict__ gw, const float* __restrict__ gb){
  int w = (blockIdx.x*blockDim.x + threadIdx.x) >> 5;
  int lane = threadIdx.x & 31;
  if(w >= NB) return;
  const float* f0 = d_fea1 + (size_t)w*D1;
  const float* f1 = d_fea1 + (size_t)NB*D1 + (size_t)w*D1;
  float acc[16];
  #pragma unroll
  for(int j=0;j<16;j++) acc[j]=0.f;
  for(int k=lane;k<D1;k+=32){
    float v0 = f0[k], v1 = f1[k];
    const float* g0 = gw + k*8;
    const float* g1 = gw + D1*8 + k*8;
    #pragma unroll
    for(int j=0;j<8;j++){ acc[j] += v0*g0[j]; acc[8+j] += v1*g1[j]; }
  }
  warp_reduce16(acc);
  if(lane==0){
    float l[8], o[8];
    #pragma unroll
    for(int t=0;t<2;t++){
      #pragma unroll
      for(int j=0;j<8;j++) l[j] = acc[t*8+j] + gb[t*8+j];
      softmax8(l,o);
      #pragma unroll
      for(int j=0;j<8;j++) d_gate1[(size_t)w*16 + t*8 + j] = o[j];
    }
  }
}

// SIMT SGEMM for the small tower layers: mode 2 / mode 3 (with fused stats).
__global__ void __launch_bounds__(256,2) sgemm_kernel(int mode, const float* __restrict__ w_base){
  __shared__ float sh[2048];
  float* As = sh;
  float* Bs = sh + 1024;

  const int z = blockIdx.z;
  const float* A; const float* W; float* C; float* sumP; float* sqP;
  int N, K;
  if(mode==2){
    A=d_fea2 + (size_t)z*NB*D2; K=D2; N=128;
    W=w_base + (size_t)z*K*N; C=d_t1raw + (size_t)z*NB*N;
    sumP=d_sumT0 + z*N; sqP=d_sqT0 + z*N;
  } else {
    A=d_t1 + (size_t)z*NB*128; K=128; N=64;
    W=w_base + (size_t)z*K*N; C=d_t2raw + (size_t)z*NB*N;
    sumP=d_sumT1 + z*N; sqP=d_sqT1 + z*N;
  }

  const int tid = threadIdx.x;
  const int tx = tid & 15, ty = tid >> 4;
  const int m0 = blockIdx.y*128, n0 = blockIdx.x*128;
  const int arow = tid >> 1, acol = (tid & 1)*4;
  const int brow = tid >> 5, bcol = (tid & 31)*4;

  float acc[8][8];
  #pragma unroll
  for(int i=0;i<8;i++)
    #pragma unroll
    for(int j=0;j<8;j++) acc[i][j]=0.f;

  const float* Aptr = A + (size_t)(m0+arow)*K + acol;
  const bool bload = (n0 + bcol) < N;

  for(int k0=0; k0<K; k0+=8){
    float4 av = *(const float4*)(Aptr + k0);
    As[(acol+0)*128 + arow] = av.x;
    As[(acol+1)*128 + arow] = av.y;
    As[(acol+2)*128 + arow] = av.z;
    As[(acol+3)*128 + arow] = av.w;
    float4 bv = bload ? *(const float4*)(W + (size_t)(k0+brow)*N + n0 + bcol)
                      : make_float4(0.f,0.f,0.f,0.f);
    *(float4*)(Bs + brow*128 + bcol) = bv;
    __syncthreads();
    #pragma unroll
    for(int kk=0;kk<8;kk++){
      float a[8], bb[8];
      *(float4*)(a)    = *(float4*)(As + kk*128 + ty*8);
      *(float4*)(a+4)  = *(float4*)(As + kk*128 + ty*8 + 4);
      *(float4*)(bb)   = *(float4*)(Bs + kk*128 + tx*8);
      *(float4*)(bb+4) = *(float4*)(Bs + kk*128 + tx*8 + 4);
      #pragma unroll
      for(int i=0;i<8;i++)
        #pragma unroll
        for(int j=0;j<8;j++) acc[i][j] += a[i]*bb[j];
    }
    __syncthreads();
  }

  float s1[8], s2[8];
  #pragma unroll
  for(int j=0;j<8;j++){ s1[j]=0.f; s2[j]=0.f; }
  const bool wok = (n0 + tx*8) < N;
  #pragma unroll
  for(int i=0;i<8;i++){
    int m = m0 + ty*8 + i;
    #pragma unroll
    for(int j=0;j<8;j++){ float v = acc[i][j]; s1[j]+=v; s2[j]+=v*v; }
    if(wok){
      *(float4*)(C + (size_t)m*N + n0 + tx*8)     = *(float4*)&acc[i][0];
      *(float4*)(C + (size_t)m*N + n0 + tx*8 + 4) = *(float4*)&acc[i][4];
    }
  }
  __syncthreads();
  #pragma unroll
  for(int j=0;j<8;j++) sh[ty*128 + tx*8 + j] = s1[j];
  __syncthreads();
  if(tid < 128 && (n0 + tid) < N){
    float t = 0.f;
    #pragma unroll
    for(int r=0;r<16;r++) t += sh[r*128 + tid];
    atomicAdd(&sumP[n0 + tid], t);
  }
  __syncthreads();
  #pragma unroll
  for(int j=0;j<8;j++) sh[ty*128 + tx*8 + j] = s2[j];
  __syncthreads();
  if(tid < 128 && (n0 + tid) < N){
    float t = 0.f;
    #pragma unroll
    for(int r=0;r<16;r++) t += sh[r*128 + tid];
    atomicAdd(&sqP[n0 + tid], t);
  }
}

__global__ void finalize_kernel(int mode, const float* __restrict__ g, const float* __restrict__ bt){
  int i = blockIdx.x*blockDim.x + threadIdx.x;
  const float* sum; const float* sq; float* a; float* c; int N, NZ;
  if(mode==0){ sum=d_sum0; sq=d_sq0; a=d_a0; c=d_c0; N=D1; NZ=12; }
  else if(mode==1){ sum=d_sum1; sq=d_sq1; a=d_a1; c=d_c1; N=D2; NZ=16; }
  else if(mode==2){ sum=d_sumT0; sq=d_sqT0; a=d_aT0; c=d_cT0; N=128; NZ=2; }
  else { sum=d_sumT1; sq=d_sqT1; a=d_aT1; c=d_cT1; N=64; NZ=2; }
  if(i >= NZ*N) return;
  int z = i / N, o = i - z*N;
  int gz = (mode==1) ? expert_of(z) : z;
  float mu  = sum[i] * (1.f/NB);
  float var = sq[i] * (1.f/NB) - mu*mu;
  float aa  = g[gz*N+o] * rsqrtf(var + 1e-5f);
  a[i] = aa;
  c[i] = bt[gz*N+o] - mu*aa;
}

__global__ void combine0_kernel(){
  int idx = blockIdx.x*blockDim.x + threadIdx.x;
  int o = idx & (D1-1);
  size_t b = (size_t)(idx >> 9);
  const float* g = d_gate0 + b*16;
  float acc0 = 0.f, acc1 = 0.f;
  #pragma unroll
  for(int e=0;e<12;e++){
    float h = d_h0[((size_t)e*NB + b)*D1 + o];
    float y = fmaxf(h*d_a0[e*D1+o] + d_c0[e*D1+o], 0.f);
    if(e < 4)       acc0 += g[e]*y;
    else if(e < 8)  acc1 += g[8 + e - 4]*y;
    else { acc0 += g[e-4]*y; acc1 += g[8 + e - 4]*y; }
  }
  d_fea1[b*D1 + o] = acc0;
  d_fea1[(size_t)NB*D1 + b*D1 + o] = acc1;
}

__global__ void combine1_kernel(){
  int idx = blockIdx.x*blockDim.x + threadIdx.x;
  int o = idx & (D2-1);
  size_t b = (size_t)(idx >> 8);
  const float* g = d_gate1 + b*16;
  float acc0 = 0.f, acc1 = 0.f;
  #pragma unroll
  for(int s=0;s<16;s++){
    float h = d_h1[((size_t)s*NB + b)*D2 + o];
    float y = fmaxf(h*d_a1[s*D2+o] + d_c1[s*D2+o], 0.f);
    if(s < 8) acc0 += g[s]*y; else acc1 += g[s]*y;
  }
  d_fea2[b*D2 + o] = acc0;
  d_fea2[(size_t)NB*D2 + b*D2 + o] = acc1;
}

__global__ void normrelu_kernel(int mode){
  int i = blockIdx.x*blockDim.x + threadIdx.x;
  if(mode==0){
    if(i >= 2*NB*128) return;
    int o = i & 127; int t = i / (NB*128);
    d_t1[i] = fmaxf(d_t1raw[i]*d_aT0[t*128+o] + d_cT0[t*128+o], 0.f);
  } else {
    if(i >= 2*NB*64) return;
    int o = i & 63; int t = i / (NB*64);
    d_t2[i] = fmaxf(d_t2raw[i]*d_aT1[t*64+o] + d_cT1[t*64+o], 0.f);
  }
}

__global__ void final_kernel(const float* __restrict__ tow, const float* __restrict__ tob,
                             float* __restrict__ out){
  int w = (blockIdx.x*blockDim.x + threadIdx.x) >> 5;
  int lane = threadIdx.x & 31;
  if(w >= NB) return;
  size_t b = (size_t)w;
  float s0 = d_t2[b*64 + lane]*tow[lane] + d_t2[b*64 + lane + 32]*tow[lane + 32];
  float s1 = d_t2[(size_t)NB*64 + b*64 + lane]*tow[64 + lane]
           + d_t2[(size_t)NB*64 + b*64 + lane + 32]*tow[64 + lane + 32];
  #pragma unroll
  for(int off=16; off; off>>=1){
    s0 += __shfl_xor_sync(0xffffffffu, s0, off);
    s1 += __shfl_xor_sync(0xffffffffu, s1, off);
  }
  if(lane==0){
    out[b]      = 1.f/(1.f + expf(-(s0 + tob[0])));
    out[NB + b] = 1.f/(1.f + expf(-(s1 + tob[1])));
  }
}

// ---------------- host launcher ----------------
extern "C" void kernel_launch(void* const* d_in, const int* in_sizes, int n_in,
                              void* d_out, int out_size){
  const int*   x    = (const int*)  d_in[0];
  const float* emb  = (const float*)d_in[1];
  const float* ew0  = (const float*)d_in[2];
  const float* eg0  = (const float*)d_in[4];
  const float* ebt0 = (const float*)d_in[5];
  const float* gw0  = (const float*)d_in[6];
  const float* gb0  = (const float*)d_in[7];
  const float* ew1  = (const float*)d_in[10];
  const float* eg1  = (const float*)d_in[12];
  const float* ebt1 = (const float*)d_in[13];
  const float* gw1  = (const float*)d_in[14];
  const float* gb1  = (const float*)d_in[15];
  const float* tw0  = (const float*)d_in[18];
  const float* tg0  = (const float*)d_in[20];
  const float* tbt0 = (const float*)d_in[21];
  const float* tw1  = (const float*)d_in[22];
  const float* tg1  = (const float*)d_in[24];
  const float* tbt1 = (const float*)d_in[25];
  const float* tow  = (const float*)d_in[26];
  const float* tob  = (const float*)d_in[27];
  float* out = (float*)d_out;

  static bool attr_set = false;
  if(!attr_set){
    cudaFuncSetAttribute(wmma_gemm_kernel, cudaFuncAttributeMaxDynamicSharedMemorySize, SMEM_GEMM_BYTES);
    attr_set = true;
  }

  zero_stats_kernel<<<(12*D1 + 255)/256, 256>>>();
  gather_kernel<<<(NB*NF*NE)/256, 256>>>(x, emb);
  gate0_kernel<<<(NB*32)/256, 256>>>(gw0, gb0);

  wmma_gemm_kernel<<<dim3(D1/BN, NB/BM, 12), 256, SMEM_GEMM_BYTES>>>(0, ew0);
  colsum_kernel<<<dim3(D1/256, NB/256, 12), 256>>>(0);
  finalize_kernel<<<(12*D1 + 255)/256, 256>>>(0, eg0, ebt0);
  combine0_kernel<<<(NB*D1)/256, 256>>>();

  gate1_kernel<<<(NB*32)/256, 256>>>(gw1, gb1);
  wmma_gemm_kernel<<<dim3(D2/BN, NB/BM, 16), 256, SMEM_GEMM_BYTES>>>(1, ew1);
  colsum_kernel<<<dim3(D2/256, NB/256, 16), 256>>>(1);
  finalize_kernel<<<(16*D2 + 255)/256, 256>>>(1, eg1, ebt1);
  combine1_kernel<<<(NB*D2)/256, 256>>>();

  sgemm_kernel<<<dim3(1, NB/128, 2), 256>>>(2, tw0);
  finalize_kernel<<<1, 256>>>(2, tg0, tbt0);
  normrelu_kernel<<<(2*NB*128)/256, 256>>>(0);

  sgemm_kernel<<<dim3(1, NB/128, 2), 256>>>(3, tw1);
  finalize_kernel<<<1, 256>>>(3, tg1, tbt1);
  normrelu_kernel<<<(2*NB*64)/256, 256>>>(1);

  final_kernel<<<(NB*32)/256, 256>>>(tow, tob, out);
}

// round 4
// speedup vs baseline: 1.6850x; 1.0383x over previous
#include <cuda_runtime.h>
#include <mma.h>
#include <math.h>
#include <stdint.h>

using namespace nvcuda;

// Problem constants
constexpr int NB   = 16384;
constexpr int NF   = 18;
constexpr int NE   = 64;
constexpr int IN0  = 1152;
constexpr int D1   = 512;
constexpr int D2   = 256;
constexpr int NVOC = 100000;

// ---------------- static device scratch ----------------
__device__ __align__(1024) float d_feat [(size_t)NB*IN0];
__device__ __align__(1024) float d_h0   [(size_t)12*NB*D1];
__device__ __align__(1024) float d_h1   [(size_t)16*NB*D2];
__device__ __align__(1024) float d_fea1 [(size_t)2*NB*D1];
__device__ __align__(1024) float d_fea2 [(size_t)2*NB*D2];
__device__ __align__(1024) float d_w0r  [(size_t)12*IN0*D1];   // tf32-rounded ew0
__device__ __align__(1024) float d_w1r  [(size_t)12*D1*D2];    // tf32-rounded ew1
__device__ float d_t1raw[(size_t)2*NB*128];
__device__ float d_t1   [(size_t)2*NB*128];
__device__ float d_t2raw[(size_t)2*NB*64];
__device__ float d_t2   [(size_t)2*NB*64];
__device__ float d_gate0[(size_t)NB*16];
__device__ float d_gate1[(size_t)NB*16];

__device__ float d_sum0[12*D1], d_sq0[12*D1], d_a0[12*D1], d_c0[12*D1];
__device__ float d_sum1[16*D2], d_sq1[16*D2], d_a1[16*D2], d_c1[16*D2];
__device__ float d_sumT0[2*128], d_sqT0[2*128], d_aT0[2*128], d_cT0[2*128];
__device__ float d_sumT1[2*64],  d_sqT1[2*64],  d_aT1[2*64],  d_cT1[2*64];

__device__ __forceinline__ int expert_of(int z){
  int t = z >> 3, k = z & 7;
  return (k < 4) ? (t*4 + k) : (4 + k);
}

__device__ __forceinline__ float to_tf32(float v){
  float r; asm("cvt.rna.tf32.f32 %0, %1;" : "=f"(r) : "f"(v)); return r;
}

// ---------------- cp.async helpers ----------------
__device__ __forceinline__ uint32_t smem_u32(const void* p){
  uint32_t a;
  asm("{ .reg .u64 t; cvta.to.shared.u64 t, %1; cvt.u32.u64 %0, t; }" : "=r"(a) : "l"(p));
  return a;
}
__device__ __forceinline__ void cp16(uint32_t s, const void* g){
  asm volatile("cp.async.cg.shared.global [%0], [%1], 16;" :: "r"(s), "l"(g) : "memory");
}
#define CP_COMMIT() asm volatile("cp.async.commit_group;" ::: "memory")
#define CP_WAIT(n)  asm volatile("cp.async.wait_group %0;" :: "n"(n) : "memory")

// ---------------- wmma tf32 grouped GEMM ----------------
// C[z][M,N] = A[z][M,K] @ W[z][K,N]; inputs pre-rounded to tf32 (rna) so no
// in-loop conversion is needed (HW truncation of rounded values is exact).
constexpr int BM = 128, BN = 128, BK = 32;
constexpr int A_LD = 36;
constexpr int B_LD = 132;
constexpr int A_STAGE = BM * A_LD;       // 4608 floats
constexpr int B_STAGE = BK * B_LD;       // 4224 floats
constexpr int SMEM_GEMM_FLOATS = 2*A_STAGE + 2*B_STAGE;
constexpr int SMEM_GEMM_BYTES  = SMEM_GEMM_FLOATS * 4;    // 70656

typedef wmma::fragment<wmma::matrix_a, 16,16,8, wmma::precision::tf32, wmma::row_major> FragA;
typedef wmma::fragment<wmma::matrix_b, 16,16,8, wmma::precision::tf32, wmma::row_major> FragB;
typedef wmma::fragment<wmma::accumulator, 16,16,8, float> FragC;

__global__ void __launch_bounds__(256,2) wmma_gemm_kernel(int mode,
                                                          const float* __restrict__ w0,
                                                          const float* __restrict__ w1){
  extern __shared__ float sh[];
  const uint32_t sb = smem_u32(sh);
  const int tid = threadIdx.x;
  const int wid = tid >> 5;
  const int wm = wid >> 2;     // 0..1 -> 64-row slice
  const int wn = wid & 3;      // 0..3 -> 32-col slice

  const int z = blockIdx.z;
  const float* A; const float* W; float* C;
  int N, K;
  if(mode == 0){
    A = d_feat; K = IN0; N = D1;
    W = w0 + (size_t)z*K*N;
    C = d_h0 + (size_t)z*NB*N;
  } else {
    int t = z >> 3, e = expert_of(z);
    A = d_fea1 + (size_t)t*NB*D1; K = D1; N = D2;
    W = w1 + (size_t)e*K*N;
    C = d_h1 + (size_t)z*NB*N;
  }
  const int NK = K / BK;
  const int m0 = blockIdx.y * BM;
  const int n0 = blockIdx.x * BN;

  const float* Abase = A + (size_t)m0 * K;
  const float* Bbase = W + n0;

  auto load_stage = [&](int kc, int buf){
    const float* gA = Abase + (size_t)kc * BK;
    const float* gB = Bbase + (size_t)kc * BK * N;
    uint32_t sA = sb + buf * (A_STAGE*4);
    uint32_t sB = sb + 2*(A_STAGE*4) + buf * (B_STAGE*4);
    #pragma unroll
    for(int it = 0; it < 4; ++it){
      int idx = it*256 + tid;
      int r = idx >> 3, q = idx & 7;
      cp16(sA + (uint32_t)(r*A_LD + q*4)*4, gA + (size_t)r*K + q*4);
    }
    #pragma unroll
    for(int it = 0; it < 4; ++it){
      int idx = it*256 + tid;
      int r = idx >> 5, q = idx & 31;
      cp16(sB + (uint32_t)(r*B_LD + q*4)*4, gB + (size_t)r*N + q*4);
    }
  };

  FragC acc[4][2];
  #pragma unroll
  for(int i = 0; i < 4; ++i)
    #pragma unroll
    for(int j = 0; j < 2; ++j) wmma::fill_fragment(acc[i][j], 0.f);

  load_stage(0, 0);
  CP_COMMIT();

  for(int kc = 0; kc < NK; ++kc){
    if(kc + 1 < NK){
      load_stage(kc+1, (kc+1) & 1);
      CP_COMMIT();
      CP_WAIT(1);
    } else {
      CP_WAIT(0);
    }
    __syncthreads();
    const float* As = sh + (kc & 1) * A_STAGE;
    const float* Bs = sh + 2*A_STAGE + (kc & 1) * B_STAGE;
    #pragma unroll
    for(int ks = 0; ks < 4; ++ks){
      FragB b0, b1;
      wmma::load_matrix_sync(b0, Bs + (ks*8)*B_LD + wn*32, B_LD);
      wmma::load_matrix_sync(b1, Bs + (ks*8)*B_LD + wn*32 + 16, B_LD);
      #pragma unroll
      for(int im = 0; im < 4; ++im){
        FragA a;
        wmma::load_matrix_sync(a, As + (wm*64 + im*16)*A_LD + ks*8, A_LD);
        wmma::mma_sync(acc[im][0], a, b0, acc[im][0]);
        wmma::mma_sync(acc[im][1], a, b1, acc[im][1]);
      }
    }
    __syncthreads();
  }

  #pragma unroll
  for(int im = 0; im < 4; ++im)
    #pragma unroll
    for(int jn = 0; jn < 2; ++jn)
      wmma::store_matrix_sync(C + (size_t)(m0 + wm*64 + im*16)*N + (n0 + wn*32 + jn*16),
                              acc[im][jn], N, wmma::mem_row_major);
}

// round weights to tf32 (rna) into scratch
__global__ void round_w_kernel(const float* __restrict__ src, float* __restrict__ dst, int n){
  int i = blockIdx.x*blockDim.x + threadIdx.x;
  if(i < n) dst[i] = to_tf32(src[i]);
}

// ---------------- BN column stats over h (sum / sumsq) ----------------
__global__ void colsum_kernel(int mode){
  int z = blockIdx.z;
  const float* H; float* sum; float* sq; int N;
  if(mode == 0){ H = d_h0 + (size_t)z*NB*D1; sum = d_sum0 + z*D1; sq = d_sq0 + z*D1; N = D1; }
  else         { H = d_h1 + (size_t)z*NB*D2; sum = d_sum1 + z*D2; sq = d_sq1 + z*D2; N = D2; }
  int col = blockIdx.x*256 + threadIdx.x;
  const float* p = H + (size_t)blockIdx.y*256*N + col;
  float s = 0.f, q = 0.f;
  #pragma unroll 8
  for(int r = 0; r < 256; ++r){ float v = p[(size_t)r*N]; s += v; q += v*v; }
  atomicAdd(&sum[col], s);
  atomicAdd(&sq[col], q);
}

// ---------------- small kernels ----------------
__global__ void zero_stats_kernel(){
  int i = blockIdx.x*blockDim.x + threadIdx.x;
  if(i < 12*D1){ d_sum0[i]=0.f; d_sq0[i]=0.f; }
  if(i < 16*D2){ d_sum1[i]=0.f; d_sq1[i]=0.f; }
  if(i < 2*128){ d_sumT0[i]=0.f; d_sqT0[i]=0.f; }
  if(i < 2*64 ){ d_sumT1[i]=0.f; d_sqT1[i]=0.f; }
}

__global__ void gather_kernel(const int* __restrict__ x, const float* __restrict__ emb){
  int idx = blockIdx.x*blockDim.x + threadIdx.x;
  int e = idx & (NE-1);
  int f = (idx >> 6) % NF;
  int b = idx / (NE*NF);
  int v = x[b*NF + f];
  d_feat[(size_t)b*IN0 + f*NE + e] = to_tf32(emb[((size_t)f*NVOC + (size_t)v)*NE + e]);
}

__device__ __forceinline__ void warp_reduce16(float* acc){
  #pragma unroll
  for(int off=16; off; off>>=1)
    #pragma unroll
    for(int j=0;j<16;j++) acc[j] += __shfl_xor_sync(0xffffffffu, acc[j], off);
}
__device__ __forceinline__ void softmax8(const float* l, float* o){
  float m = l[0];
  #pragma unroll
  for(int j=1;j<8;j++) m = fmaxf(m, l[j]);
  float s = 0.f, e[8];
  #pragma unroll
  for(int j=0;j<8;j++){ e[j] = expf(l[j]-m); s += e[j]; }
  float inv = 1.f/s;
  #pragma unroll
  for(int j=0;j<8;j++) o[j] = e[j]*inv;
}

__global__ void gate0_kernel(const float* __restrict__ gw, const float* __restrict__ gb){
  int w = (blockIdx.x*blockDim.x + threadIdx.x) >> 5;
  int lane = threadIdx.x & 31;
  if(w >= NB) return;
  const float* frow = d_feat + (size_t)w*IN0;
  float acc[16];
  #pragma unroll
  for(int j=0;j<16;j++) acc[j]=0.f;
  for(int k=lane;k<IN0;k+=32){
    float fv = frow[k];
    const float* g0 = gw + k*8;
    const float* g1 = gw + IN0*8 + k*8;
    #pragma unroll
    for(int j=0;j<8;j++){ acc[j] += fv*g0[j]; acc[8+j] += fv*g1[j]; }
  }
  warp_reduce16(acc);
  if(lane==0){
    float l[8], o[8];
    #pragma unroll
    for(int t=0;t<2;t++){
      #pragma unroll
      for(int j=0;j<8;j++) l[j] = acc[t*8+j] + gb[t*8+j];
      softmax8(l,o);
      #pragma unroll
      for(int j=0;j<8;j++) d_gate0[(size_t)w*16 + t*8 + j] = o[j];
    }
  }
}

__global__ void gate1_kernel(const float* __restrict__ gw, const float* __restrict__ gb){
  int w = (blockIdx.x*blockDim.x + threadIdx.x) >> 5;
  int lane = threadIdx.x & 31;
  if(w >= NB) return;
  const float* f0 = d_fea1 + (size_t)w*D1;
  const float* f1 = d_fea1 + (size_t)NB*D1 + (size_t)w*D1;
  float acc[16];
  #pragma unroll
  for(int j=0;j<16;j++) acc[j]=0.f;
  for(int k=lane;k<D1;k+=32){
    float v0 = f0[k], v1 = f1[k];
    const float* g0 = gw + k*8;
    const float* g1 = gw + D1*8 + k*8;
    #pragma unroll
    for(int j=0;j<8;j++){ acc[j] += v0*g0[j]; acc[8+j] += v1*g1[j]; }
  }
  warp_reduce16(acc);
  if(lane==0){
    float l[8], o[8];
    #pragma unroll
    for(int t=0;t<2;t++){
      #pragma unroll
      for(int j=0;j<8;j++) l[j] = acc[t*8+j] + gb[t*8+j];
      softmax8(l,o);
      #pragma unroll
      for(int j=0;j<8;j++) d_gate1[(size_t)w*16 + t*8 + j] = o[j];
    }
  }
}

// SIMT SGEMM for the small tower layers: mode 2 / mode 3 (with fused stats).
__global__ void __launch_bounds__(256,2) sgemm_kernel(int mode, const float* __restrict__ w_base){
  __shared__ float sh[2048];
  float* As = sh;
  float* Bs = sh + 1024;

  const int z = blockIdx.z;
  const float* A; const float* W; float* C; float* sumP; float* sqP;
  int N, K;
  if(mode==2){
    A=d_fea2 + (size_t)z*NB*D2; K=D2; N=128;
    W=w_base + (size_t)z*K*N; C=d_t1raw + (size_t)z*NB*N;
    sumP=d_sumT0 + z*N; sqP=d_sqT0 + z*N;
  } else {
    A=d_t1 + (size_t)z*NB*128; K=128; N=64;
    W=w_base + (size_t)z*K*N; C=d_t2raw + (size_t)z*NB*N;
    sumP=d_sumT1 + z*N; sqP=d_sqT1 + z*N;
  }

  const int tid = threadIdx.x;
  const int tx = tid & 15, ty = tid >> 4;
  const int m0 = blockIdx.y*128, n0 = blockIdx.x*128;
  const int arow = tid >> 1, acol = (tid & 1)*4;
  const int brow = tid >> 5, bcol = (tid & 31)*4;

  float acc[8][8];
  #pragma unroll
  for(int i=0;i<8;i++)
    #pragma unroll
    for(int j=0;j<8;j++) acc[i][j]=0.f;

  const float* Aptr = A + (size_t)(m0+arow)*K + acol;
  const bool bload = (n0 + bcol) < N;

  for(int k0=0; k0<K; k0+=8){
    float4 av = *(const float4*)(Aptr + k0);
    As[(acol+0)*128 + arow] = av.x;
    As[(acol+1)*128 + arow] = av.y;
    As[(acol+2)*128 + arow] = av.z;
    As[(acol+3)*128 + arow] = av.w;
    float4 bv = bload ? *(const float4*)(W + (size_t)(k0+brow)*N + n0 + bcol)
                      : make_float4(0.f,0.f,0.f,0.f);
    *(float4*)(Bs + brow*128 + bcol) = bv;
    __syncthreads();
    #pragma unroll
    for(int kk=0;kk<8;kk++){
      float a[8], bb[8];
      *(float4*)(a)    = *(float4*)(As + kk*128 + ty*8);
      *(float4*)(a+4)  = *(float4*)(As + kk*128 + ty*8 + 4);
      *(float4*)(bb)   = *(float4*)(Bs + kk*128 + tx*8);
      *(float4*)(bb+4) = *(float4*)(Bs + kk*128 + tx*8 + 4);
      #pragma unroll
      for(int i=0;i<8;i++)
        #pragma unroll
        for(int j=0;j<8;j++) acc[i][j] += a[i]*bb[j];
    }
    __syncthreads();
  }

  float s1[8], s2[8];
  #pragma unroll
  for(int j=0;j<8;j++){ s1[j]=0.f; s2[j]=0.f; }
  const bool wok = (n0 + tx*8) < N;
  #pragma unroll
  for(int i=0;i<8;i++){
    int m = m0 + ty*8 + i;
    #pragma unroll
    for(int j=0;j<8;j++){ float v = acc[i][j]; s1[j]+=v; s2[j]+=v*v; }
    if(wok){
      *(float4*)(C + (size_t)m*N + n0 + tx*8)     = *(float4*)&acc[i][0];
      *(float4*)(C + (size_t)m*N + n0 + tx*8 + 4) = *(float4*)&acc[i][4];
    }
  }
  __syncthreads();
  #pragma unroll
  for(int j=0;j<8;j++) sh[ty*128 + tx*8 + j] = s1[j];
  __syncthreads();
  if(tid < 128 && (n0 + tid) < N){
    float t = 0.f;
    #pragma unroll
    for(int r=0;r<16;r++) t += sh[r*128 + tid];
    atomicAdd(&sumP[n0 + tid], t);
  }
  __syncthreads();
  #pragma unroll
  for(int j=0;j<8;j++) sh[ty*128 + tx*8 + j] = s2[j];
  __syncthreads();
  if(tid < 128 && (n0 + tid) < N){
    float t = 0.f;
    #pragma unroll
    for(int r=0;r<16;r++) t += sh[r*128 + tid];
    atomicAdd(&sqP[n0 + tid], t);
  }
}

__global__ void finalize_kernel(int mode, const float* __restrict__ g, const float* __restrict__ bt){
  int i = blockIdx.x*blockDim.x + threadIdx.x;
  const float* sum; const float* sq; float* a; float* c; int N, NZ;
  if(mode==0){ sum=d_sum0; sq=d_sq0; a=d_a0; c=d_c0; N=D1; NZ=12; }
  else if(mode==1){ sum=d_sum1; sq=d_sq1; a=d_a1; c=d_c1; N=D2; NZ=16; }
  else if(mode==2){ sum=d_sumT0; sq=d_sqT0; a=d_aT0; c=d_cT0; N=128; NZ=2; }
  else { sum=d_sumT1; sq=d_sqT1; a=d_aT1; c=d_cT1; N=64; NZ=2; }
  if(i >= NZ*N) return;
  int z = i / N, o = i - z*N;
  int gz = (mode==1) ? expert_of(z) : z;
  float mu  = sum[i] * (1.f/NB);
  float var = sq[i] * (1.f/NB) - mu*mu;
  float aa  = g[gz*N+o] * rsqrtf(var + 1e-5f);
  a[i] = aa;
  c[i] = bt[gz*N+o] - mu*aa;
}

__global__ void combine0_kernel(){
  int idx = blockIdx.x*blockDim.x + threadIdx.x;
  int o = idx & (D1-1);
  size_t b = (size_t)(idx >> 9);
  const float* g = d_gate0 + b*16;
  float acc0 = 0.f, acc1 = 0.f;
  #pragma unroll
  for(int e=0;e<12;e++){
    float h = d_h0[((size_t)e*NB + b)*D1 + o];
    float y = fmaxf(h*d_a0[e*D1+o] + d_c0[e*D1+o], 0.f);
    if(e < 4)       acc0 += g[e]*y;
    else if(e < 8)  acc1 += g[8 + e - 4]*y;
    else { acc0 += g[e-4]*y; acc1 += g[8 + e - 4]*y; }
  }
  d_fea1[b*D1 + o] = to_tf32(acc0);
  d_fea1[(size_t)NB*D1 + b*D1 + o] = to_tf32(acc1);
}

__global__ void combine1_kernel(){
  int idx = blockIdx.x*blockDim.x + threadIdx.x;
  int o = idx & (D2-1);
  size_t b = (size_t)(idx >> 8);
  const float* g = d_gate1 + b*16;
  float acc0 = 0.f, acc1 = 0.f;
  #pragma unroll
  for(int s=0;s<16;s++){
    float h = d_h1[((size_t)s*NB + b)*D2 + o];
    float y = fmaxf(h*d_a1[s*D2+o] + d_c1[s*D2+o], 0.f);
    if(s < 8) acc0 += g[s]*y; else acc1 += g[s]*y;
  }
  d_fea2[b*D2 + o] = acc0;
  d_fea2[(size_t)NB*D2 + b*D2 + o] = acc1;
}

__global__ void normrelu_kernel(int mode){
  int i = blockIdx.x*blockDim.x + threadIdx.x;
  if(mode==0){
    if(i >= 2*NB*128) return;
    int o = i & 127; int t = i / (NB*128);
    d_t1[i] = fmaxf(d_t1raw[i]*d_aT0[t*128+o] + d_cT0[t*128+o], 0.f);
  } else {
    if(i >= 2*NB*64) return;
    int o = i & 63; int t = i / (NB*64);
    d_t2[i] = fmaxf(d_t2raw[i]*d_aT1[t*64+o] + d_cT1[t*64+o], 0.f);
  }
}

__global__ void final_kernel(const float* __restrict__ tow, const float* __restrict__ tob,
                             float* __restrict__ out){
  int w = (blockIdx.x*blockDim.x + threadIdx.x) >> 5;
  int lane = threadIdx.x & 31;
  if(w >= NB) return;
  size_t b = (size_t)w;
  float s0 = d_t2[b*64 + lane]*tow[lane] + d_t2[b*64 + lane + 32]*tow[lane + 32];
  float s1 = d_t2[(size_t)NB*64 + b*64 + lane]*tow[64 + lane]
           + d_t2[(size_t)NB*64 + b*64 + lane + 32]*tow[64 + lane + 32];
  #pragma unroll
  for(int off=16; off; off>>=1){
    s0 += __shfl_xor_sync(0xffffffffu, s0, off);
    s1 += __shfl_xor_sync(0xffffffffu, s1, off);
  }
  if(lane==0){
    out[b]      = 1.f/(1.f + expf(-(s0 + tob[0])));
    out[NB + b] = 1.f/(1.f + expf(-(s1 + tob[1])));
  }
}

// ---------------- host launcher ----------------
extern "C" void kernel_launch(void* const* d_in, const int* in_sizes, int n_in,
                              void* d_out, int out_size){
  const int*   x    = (const int*)  d_in[0];
  const float* emb  = (const float*)d_in[1];
  const float* ew0  = (const float*)d_in[2];
  const float* eg0  = (const float*)d_in[4];
  const float* ebt0 = (const float*)d_in[5];
  const float* gw0  = (const float*)d_in[6];
  const float* gb0  = (const float*)d_in[7];
  const float* ew1  = (const float*)d_in[10];
  const float* eg1  = (const float*)d_in[12];
  const float* ebt1 = (const float*)d_in[13];
  const float* gw1  = (const float*)d_in[14];
  const float* gb1  = (const float*)d_in[15];
  const float* tw0  = (const float*)d_in[18];
  const float* tg0  = (const float*)d_in[20];
  const float* tbt0 = (const float*)d_in[21];
  const float* tw1  = (const float*)d_in[22];
  const float* tg1  = (const float*)d_in[24];
  const float* tbt1 = (const float*)d_in[25];
  const float* tow  = (const float*)d_in[26];
  const float* tob  = (const float*)d_in[27];
  float* out = (float*)d_out;

  static bool attr_set = false;
  if(!attr_set){
    cudaFuncSetAttribute(wmma_gemm_kernel, cudaFuncAttributeMaxDynamicSharedMemorySize, SMEM_GEMM_BYTES);
    attr_set = true;
  }

  float* w0r; cudaGetSymbolAddress((void**)&w0r, d_w0r);
  float* w1r; cudaGetSymbolAddress((void**)&w1r, d_w1r);

  zero_stats_kernel<<<(12*D1 + 255)/256, 256>>>();
  round_w_kernel<<<(12*IN0*D1 + 255)/256, 256>>>(ew0, w0r, 12*IN0*D1);
  round_w_kernel<<<(12*D1*D2 + 255)/256, 256>>>(ew1, w1r, 12*D1*D2);
  gather_kernel<<<(NB*NF*NE)/256, 256>>>(x, emb);
  gate0_kernel<<<(NB*32)/256, 256>>>(gw0, gb0);

  wmma_gemm_kernel<<<dim3(D1/BN, NB/BM, 12), 256, SMEM_GEMM_BYTES>>>(0, w0r, w1r);
  colsum_kernel<<<dim3(D1/256, NB/256, 12), 256>>>(0);
  finalize_kernel<<<(12*D1 + 255)/256, 256>>>(0, eg0, ebt0);
  combine0_kernel<<<(NB*D1)/256, 256>>>();

  gate1_kernel<<<(NB*32)/256, 256>>>(gw1, gb1);
  wmma_gemm_kernel<<<dim3(D2/BN, NB/BM, 16), 256, SMEM_GEMM_BYTES>>>(1, w0r, w1r);
  colsum_kernel<<<dim3(D2/256, NB/256, 16), 256>>>(1);
  finalize_kernel<<<(16*D2 + 255)/256, 256>>>(1, eg1, ebt1);
  combine1_kernel<<<(NB*D2)/256, 256>>>();

  sgemm_kernel<<<dim3(1, NB/128, 2), 256>>>(2, tw0);
  finalize_kernel<<<1, 256>>>(2, tg0, tbt0);
  normrelu_kernel<<<(2*NB*128)/256, 256>>>(0);

  sgemm_kernel<<<dim3(1, NB/128, 2), 256>>>(3, tw1);
  finalize_kernel<<<1, 256>>>(3, tg1, tbt1);
  normrelu_kernel<<<(2*NB*64)/256, 256>>>(1);

  final_kernel<<<(NB*32)/256, 256>>>(tow, tob, out);
}

// round 5
// speedup vs baseline: 4.0776x; 2.4199x over previous
#include <cuda_runtime.h>
#include <cuda_bf16.h>
#include <mma.h>
#include <math.h>
#include <stdint.h>

using namespace nvcuda;

// Problem constants
constexpr int NB   = 16384;
constexpr int NF   = 18;
constexpr int NE   = 64;
constexpr int IN0  = 1152;
constexpr int D1   = 512;
constexpr int D2   = 256;
constexpr int NVOC = 100000;

// ---------------- static device scratch ----------------
__device__ __align__(1024) float d_feat [(size_t)NB*IN0];           // f32 (gates)
__device__ __align__(1024) __nv_bfloat16 d_featb[(size_t)NB*IN0];   // bf16 (MMA)
__device__ __align__(1024) float d_h0   [(size_t)12*NB*D1];
__device__ __align__(1024) float d_h1   [(size_t)16*NB*D2];
__device__ __align__(1024) float d_fea1 [(size_t)2*NB*D1];          // f32 (gate1)
__device__ __align__(1024) __nv_bfloat16 d_fea1b[(size_t)2*NB*D1];  // bf16 (MMA)
__device__ __align__(1024) float d_fea2 [(size_t)2*NB*D2];
__device__ __align__(1024) __nv_bfloat16 d_w0b[(size_t)12*IN0*D1];
__device__ __align__(1024) __nv_bfloat16 d_w1b[(size_t)12*D1*D2];
__device__ float d_t1raw[(size_t)2*NB*128];
__device__ float d_t1   [(size_t)2*NB*128];
__device__ float d_t2raw[(size_t)2*NB*64];
__device__ float d_t2   [(size_t)2*NB*64];
__device__ float d_gate0[(size_t)NB*16];
__device__ float d_gate1[(size_t)NB*16];

__device__ float d_sum0[12*D1], d_sq0[12*D1], d_a0[12*D1], d_c0[12*D1];
__device__ float d_sum1[16*D2], d_sq1[16*D2], d_a1[16*D2], d_c1[16*D2];
__device__ float d_sumT0[2*128], d_sqT0[2*128], d_aT0[2*128], d_cT0[2*128];
__device__ float d_sumT1[2*64],  d_sqT1[2*64],  d_aT1[2*64],  d_cT1[2*64];

__device__ __forceinline__ int expert_of(int z){
  int t = z >> 3, k = z & 7;
  return (k < 4) ? (t*4 + k) : (4 + k);
}

// ---------------- cp.async helpers ----------------
__device__ __forceinline__ uint32_t smem_u32(const void* p){
  uint32_t a;
  asm("{ .reg .u64 t; cvta.to.shared.u64 t, %1; cvt.u32.u64 %0, t; }" : "=r"(a) : "l"(p));
  return a;
}
__device__ __forceinline__ void cp16(uint32_t s, const void* g){
  asm volatile("cp.async.cg.shared.global [%0], [%1], 16;" :: "r"(s), "l"(g) : "memory");
}
#define CP_COMMIT() asm volatile("cp.async.commit_group;" ::: "memory")
#define CP_WAIT(n)  asm volatile("cp.async.wait_group %0;" :: "n"(n) : "memory")

// ---------------- bf16 wmma grouped GEMM, fused BN stats ----------------
// C[z][M,N] = A[z][M,K] @ W[z][K,N], bf16 inputs, f32 accumulate.
// CTA tile 128x128, BK=64 (bf16), double-buffered cp.async, 8 warps (64x32 each).
// Epilogue stages C through smem: coalesced stores + per-column sum/sumsq atomics.
constexpr int BM = 128, BN = 128, BKb = 64;
constexpr int A_LDb = 72;                      // bf16 elems per A smem row (64+8 pad)
constexpr int B_LDb = 136;                     // bf16 elems per B smem row (128+8 pad)
constexpr int A_STG_B = BM * A_LDb * 2;        // 18432 bytes
constexpr int B_STG_B = BKb * B_LDb * 2;       // 17408 bytes
constexpr int STG_B   = A_STG_B + B_STG_B;     // 35840
constexpr int PIPE_B  = 2 * STG_B;             // 71680
constexpr int EPI_B   = 128 * 132 * 4;         // 67584
constexpr int SMEM_GB = (PIPE_B > EPI_B) ? PIPE_B : EPI_B;   // 71680

typedef wmma::fragment<wmma::matrix_a, 16,16,16, __nv_bfloat16, wmma::row_major> FA;
typedef wmma::fragment<wmma::matrix_b, 16,16,16, __nv_bfloat16, wmma::row_major> FB;
typedef wmma::fragment<wmma::accumulator, 16,16,16, float> FC;

__global__ void __launch_bounds__(256,2) bf16_gemm_kernel(int mode,
                                                          const __nv_bfloat16* __restrict__ w0,
                                                          const __nv_bfloat16* __restrict__ w1){
  extern __shared__ char sm[];
  const uint32_t sb = smem_u32(sm);
  const int tid = threadIdx.x;
  const int wid = tid >> 5;
  const int wm = wid >> 2;     // 0..1 -> 64-row slice
  const int wn = wid & 3;      // 0..3 -> 32-col slice

  const int z = blockIdx.z;
  const __nv_bfloat16* A; const __nv_bfloat16* W; float* C; float* sumP; float* sqP;
  int N, K;
  if(mode == 0){
    A = d_featb; K = IN0; N = D1;
    W = w0 + (size_t)z*K*N;
    C = d_h0 + (size_t)z*NB*N;
    sumP = d_sum0 + z*N; sqP = d_sq0 + z*N;
  } else {
    int t = z >> 3, e = expert_of(z);
    A = d_fea1b + (size_t)t*NB*D1; K = D1; N = D2;
    W = w1 + (size_t)e*K*N;
    C = d_h1 + (size_t)z*NB*N;
    sumP = d_sum1 + z*N; sqP = d_sq1 + z*N;
  }
  const int NK = K / BKb;
  const int m0 = blockIdx.y * BM;
  const int n0 = blockIdx.x * BN;

  const __nv_bfloat16* Abase = A + (size_t)m0 * K;
  const __nv_bfloat16* Bbase = W + n0;

  auto load_stage = [&](int kc, int buf){
    const __nv_bfloat16* gA = Abase + (size_t)kc * BKb;
    const __nv_bfloat16* gB = Bbase + (size_t)kc * BKb * N;
    uint32_t sA = sb + buf * STG_B;
    uint32_t sB = sA + A_STG_B;
    // A: 128 rows x 8 chunks of 16B (8 bf16)
    #pragma unroll
    for(int it = 0; it < 4; ++it){
      int idx = it*256 + tid;
      int r = idx >> 3, q = idx & 7;
      cp16(sA + (uint32_t)(r*A_LDb + q*8)*2, gA + (size_t)r*K + q*8);
    }
    // B: 64 rows x 16 chunks of 16B
    #pragma unroll
    for(int it = 0; it < 4; ++it){
      int idx = it*256 + tid;
      int r = idx >> 4, q = idx & 15;
      cp16(sB + (uint32_t)(r*B_LDb + q*8)*2, gB + (size_t)r*N + q*8);
    }
  };

  FC acc[4][2];
  #pragma unroll
  for(int i = 0; i < 4; ++i)
    #pragma unroll
    for(int j = 0; j < 2; ++j) wmma::fill_fragment(acc[i][j], 0.f);

  load_stage(0, 0);
  CP_COMMIT();

  for(int kc = 0; kc < NK; ++kc){
    if(kc + 1 < NK){
      load_stage(kc+1, (kc+1) & 1);
      CP_COMMIT();
      CP_WAIT(1);
    } else {
      CP_WAIT(0);
    }
    __syncthreads();
    const __nv_bfloat16* As = (const __nv_bfloat16*)(sm + (kc & 1) * STG_B);
    const __nv_bfloat16* Bs = (const __nv_bfloat16*)(sm + (kc & 1) * STG_B + A_STG_B);
    #pragma unroll
    for(int ks = 0; ks < 4; ++ks){           // 4 x k16 per 64-K chunk
      FB b0, b1;
      wmma::load_matrix_sync(b0, Bs + (ks*16)*B_LDb + wn*32, B_LDb);
      wmma::load_matrix_sync(b1, Bs + (ks*16)*B_LDb + wn*32 + 16, B_LDb);
      #pragma unroll
      for(int im = 0; im < 4; ++im){
        FA a;
        wmma::load_matrix_sync(a, As + (wm*64 + im*16)*A_LDb + ks*16, A_LDb);
        wmma::mma_sync(acc[im][0], a, b0, acc[im][0]);
        wmma::mma_sync(acc[im][1], a, b1, acc[im][1]);
      }
    }
    __syncthreads();
  }

  // ---- epilogue: frags -> smem(f32) -> coalesced gmem + fused BN stats ----
  float* shf = (float*)sm;     // 128 x 132
  #pragma unroll
  for(int im = 0; im < 4; ++im)
    #pragma unroll
    for(int jn = 0; jn < 2; ++jn)
      wmma::store_matrix_sync(shf + (wm*64 + im*16)*132 + wn*32 + jn*16,
                              acc[im][jn], 132, wmma::mem_row_major);
  __syncthreads();

  float* Crow = C + (size_t)m0*N + n0;
  #pragma unroll 4
  for(int it = 0; it < 16; ++it){
    int idx = it*256 + tid;
    int row = idx >> 5, q = (idx & 31)*4;
    float4 v = make_float4(shf[row*132+q], shf[row*132+q+1],
                           shf[row*132+q+2], shf[row*132+q+3]);
    *(float4*)(Crow + (size_t)row*N + q) = v;
  }
  {
    int col = tid & 127, half = tid >> 7;
    float s = 0.f, q = 0.f;
    #pragma unroll 8
    for(int r = half*64; r < half*64 + 64; ++r){
      float v = shf[r*132 + col]; s += v; q += v*v;
    }
    atomicAdd(&sumP[n0 + col], s);
    atomicAdd(&sqP[n0 + col], q);
  }
}

// f32 -> bf16 conversion (weights)
__global__ void conv_bf16_kernel(const float* __restrict__ src, __nv_bfloat16* __restrict__ dst, int n){
  int i = blockIdx.x*blockDim.x + threadIdx.x;
  if(i < n) dst[i] = __float2bfloat16(src[i]);
}

// ---------------- small kernels ----------------
__global__ void zero_stats_kernel(){
  int i = blockIdx.x*blockDim.x + threadIdx.x;
  if(i < 12*D1){ d_sum0[i]=0.f; d_sq0[i]=0.f; }
  if(i < 16*D2){ d_sum1[i]=0.f; d_sq1[i]=0.f; }
  if(i < 2*128){ d_sumT0[i]=0.f; d_sqT0[i]=0.f; }
  if(i < 2*64 ){ d_sumT1[i]=0.f; d_sqT1[i]=0.f; }
}

__global__ void gather_kernel(const int* __restrict__ x, const float* __restrict__ emb){
  int idx = blockIdx.x*blockDim.x + threadIdx.x;
  int e = idx & (NE-1);
  int f = (idx >> 6) % NF;
  int b = idx / (NE*NF);
  int v = x[b*NF + f];
  float val = emb[((size_t)f*NVOC + (size_t)v)*NE + e];
  d_feat [(size_t)b*IN0 + f*NE + e] = val;
  d_featb[(size_t)b*IN0 + f*NE + e] = __float2bfloat16(val);
}

__device__ __forceinline__ void warp_reduce16(float* acc){
  #pragma unroll
  for(int off=16; off; off>>=1)
    #pragma unroll
    for(int j=0;j<16;j++) acc[j] += __shfl_xor_sync(0xffffffffu, acc[j], off);
}
__device__ __forceinline__ void softmax8(const float* l, float* o){
  float m = l[0];
  #pragma unroll
  for(int j=1;j<8;j++) m = fmaxf(m, l[j]);
  float s = 0.f, e[8];
  #pragma unroll
  for(int j=0;j<8;j++){ e[j] = expf(l[j]-m); s += e[j]; }
  float inv = 1.f/s;
  #pragma unroll
  for(int j=0;j<8;j++) o[j] = e[j]*inv;
}

__global__ void gate0_kernel(const float* __restrict__ gw, const float* __restrict__ gb){
  int w = (blockIdx.x*blockDim.x + threadIdx.x) >> 5;
  int lane = threadIdx.x & 31;
  if(w >= NB) return;
  const float* frow = d_feat + (size_t)w*IN0;
  float acc[16];
  #pragma unroll
  for(int j=0;j<16;j++) acc[j]=0.f;
  for(int k=lane;k<IN0;k+=32){
    float fv = frow[k];
    const float* g0 = gw + k*8;
    const float* g1 = gw + IN0*8 + k*8;
    #pragma unroll
    for(int j=0;j<8;j++){ acc[j] += fv*g0[j]; acc[8+j] += fv*g1[j]; }
  }
  warp_reduce16(acc);
  if(lane==0){
    float l[8], o[8];
    #pragma unroll
    for(int t=0;t<2;t++){
      #pragma unroll
      for(int j=0;j<8;j++) l[j] = acc[t*8+j] + gb[t*8+j];
      softmax8(l,o);
      #pragma unroll
      for(int j=0;j<8;j++) d_gate0[(size_t)w*16 + t*8 + j] = o[j];
    }
  }
}

__global__ void gate1_kernel(const float* __restrict__ gw, const float* __restrict__ gb){
  int w = (blockIdx.x*blockDim.x + threadIdx.x) >> 5;
  int lane = threadIdx.x & 31;
  if(w >= NB) return;
  const float* f0 = d_fea1 + (size_t)w*D1;
  const float* f1 = d_fea1 + (size_t)NB*D1 + (size_t)w*D1;
  float acc[16];
  #pragma unroll
  for(int j=0;j<16;j++) acc[j]=0.f;
  for(int k=lane;k<D1;k+=32){
    float v0 = f0[k], v1 = f1[k];
    const float* g0 = gw + k*8;
    const float* g1 = gw + D1*8 + k*8;
    #pragma unroll
    for(int j=0;j<8;j++){ acc[j] += v0*g0[j]; acc[8+j] += v1*g1[j]; }
  }
  warp_reduce16(acc);
  if(lane==0){
    float l[8], o[8];
    #pragma unroll
    for(int t=0;t<2;t++){
      #pragma unroll
      for(int j=0;j<8;j++) l[j] = acc[t*8+j] + gb[t*8+j];
      softmax8(l,o);
      #pragma unroll
      for(int j=0;j<8;j++) d_gate1[(size_t)w*16 + t*8 + j] = o[j];
    }
  }
}

// SIMT SGEMM for the small tower layers: mode 2 / mode 3 (fused stats).
__global__ void __launch_bounds__(256,2) sgemm_kernel(int mode, const float* __restrict__ w_base){
  __shared__ float sh[2048];
  float* As = sh;
  float* Bs = sh + 1024;

  const int z = blockIdx.z;
  const float* A; const float* W; float* C; float* sumP; float* sqP;
  int N, K;
  if(mode==2){
    A=d_fea2 + (size_t)z*NB*D2; K=D2; N=128;
    W=w_base + (size_t)z*K*N; C=d_t1raw + (size_t)z*NB*N;
    sumP=d_sumT0 + z*N; sqP=d_sqT0 + z*N;
  } else {
    A=d_t1 + (size_t)z*NB*128; K=128; N=64;
    W=w_base + (size_t)z*K*N; C=d_t2raw + (size_t)z*NB*N;
    sumP=d_sumT1 + z*N; sqP=d_sqT1 + z*N;
  }

  const int tid = threadIdx.x;
  const int tx = tid & 15, ty = tid >> 4;
  const int m0 = blockIdx.y*128, n0 = blockIdx.x*128;
  const int arow = tid >> 1, acol = (tid & 1)*4;
  const int brow = tid >> 5, bcol = (tid & 31)*4;

  float acc[8][8];
  #pragma unroll
  for(int i=0;i<8;i++)
    #pragma unroll
    for(int j=0;j<8;j++) acc[i][j]=0.f;

  const float* Aptr = A + (size_t)(m0+arow)*K + acol;
  const bool bload = (n0 + bcol) < N;

  for(int k0=0; k0<K; k0+=8){
    float4 av = *(const float4*)(Aptr + k0);
    As[(acol+0)*128 + arow] = av.x;
    As[(acol+1)*128 + arow] = av.y;
    As[(acol+2)*128 + arow] = av.z;
    As[(acol+3)*128 + arow] = av.w;
    float4 bv = bload ? *(const float4*)(W + (size_t)(k0+brow)*N + n0 + bcol)
                      : make_float4(0.f,0.f,0.f,0.f);
    *(float4*)(Bs + brow*128 + bcol) = bv;
    __syncthreads();
    #pragma unroll
    for(int kk=0;kk<8;kk++){
      float a[8], bb[8];
      *(float4*)(a)    = *(float4*)(As + kk*128 + ty*8);
      *(float4*)(a+4)  = *(float4*)(As + kk*128 + ty*8 + 4);
      *(float4*)(bb)   = *(float4*)(Bs + kk*128 + tx*8);
      *(float4*)(bb+4) = *(float4*)(Bs + kk*128 + tx*8 + 4);
      #pragma unroll
      for(int i=0;i<8;i++)
        #pragma unroll
        for(int j=0;j<8;j++) acc[i][j] += a[i]*bb[j];
    }
    __syncthreads();
  }

  float s1[8], s2[8];
  #pragma unroll
  for(int j=0;j<8;j++){ s1[j]=0.f; s2[j]=0.f; }
  const bool wok = (n0 + tx*8) < N;
  #pragma unroll
  for(int i=0;i<8;i++){
    int m = m0 + ty*8 + i;
    #pragma unroll
    for(int j=0;j<8;j++){ float v = acc[i][j]; s1[j]+=v; s2[j]+=v*v; }
    if(wok){
      *(float4*)(C + (size_t)m*N + n0 + tx*8)     = *(float4*)&acc[i][0];
      *(float4*)(C + (size_t)m*N + n0 + tx*8 + 4) = *(float4*)&acc[i][4];
    }
  }
  __syncthreads();
  #pragma unroll
  for(int j=0;j<8;j++) sh[ty*128 + tx*8 + j] = s1[j];
  __syncthreads();
  if(tid < 128 && (n0 + tid) < N){
    float t = 0.f;
    #pragma unroll
    for(int r=0;r<16;r++) t += sh[r*128 + tid];
    atomicAdd(&sumP[n0 + tid], t);
  }
  __syncthreads();
  #pragma unroll
  for(int j=0;j<8;j++) sh[ty*128 + tx*8 + j] = s2[j];
  __syncthreads();
  if(tid < 128 && (n0 + tid) < N){
    float t = 0.f;
    #pragma unroll
    for(int r=0;r<16;r++) t += sh[r*128 + tid];
    atomicAdd(&sqP[n0 + tid], t);
  }
}

__global__ void finalize_kernel(int mode, const float* __restrict__ g, const float* __restrict__ bt){
  int i = blockIdx.x*blockDim.x + threadIdx.x;
  const float* sum; const float* sq; float* a; float* c; int N, NZ;
  if(mode==0){ sum=d_sum0; sq=d_sq0; a=d_a0; c=d_c0; N=D1; NZ=12; }
  else if(mode==1){ sum=d_sum1; sq=d_sq1; a=d_a1; c=d_c1; N=D2; NZ=16; }
  else if(mode==2){ sum=d_sumT0; sq=d_sqT0; a=d_aT0; c=d_cT0; N=128; NZ=2; }
  else { sum=d_sumT1; sq=d_sqT1; a=d_aT1; c=d_cT1; N=64; NZ=2; }
  if(i >= NZ*N) return;
  int z = i / N, o = i - z*N;
  int gz = (mode==1) ? expert_of(z) : z;
  float mu  = sum[i] * (1.f/NB);
  float var = sq[i] * (1.f/NB) - mu*mu;
  float aa  = g[gz*N+o] * rsqrtf(var + 1e-5f);
  a[i] = aa;
  c[i] = bt[gz*N+o] - mu*aa;
}

__global__ void combine0_kernel(){
  int idx = blockIdx.x*blockDim.x + threadIdx.x;
  int o = idx & (D1-1);
  size_t b = (size_t)(idx >> 9);
  const float* g = d_gate0 + b*16;
  float acc0 = 0.f, acc1 = 0.f;
  #pragma unroll
  for(int e=0;e<12;e++){
    float h = d_h0[((size_t)e*NB + b)*D1 + o];
    float y = fmaxf(h*d_a0[e*D1+o] + d_c0[e*D1+o], 0.f);
    if(e < 4)       acc0 += g[e]*y;
    else if(e < 8)  acc1 += g[8 + e - 4]*y;
    else { acc0 += g[e-4]*y; acc1 += g[8 + e - 4]*y; }
  }
  d_fea1[b*D1 + o] = acc0;
  d_fea1[(size_t)NB*D1 + b*D1 + o] = acc1;
  d_fea1b[b*D1 + o] = __float2bfloat16(acc0);
  d_fea1b[(size_t)NB*D1 + b*D1 + o] = __float2bfloat16(acc1);
}

__global__ void combine1_kernel(){
  int idx = blockIdx.x*blockDim.x + threadIdx.x;
  int o = idx & (D2-1);
  size_t b = (size_t)(idx >> 8);
  const float* g = d_gate1 + b*16;
  float acc0 = 0.f, acc1 = 0.f;
  #pragma unroll
  for(int s=0;s<16;s++){
    float h = d_h1[((size_t)s*NB + b)*D2 + o];
    float y = fmaxf(h*d_a1[s*D2+o] + d_c1[s*D2+o], 0.f);
    if(s < 8) acc0 += g[s]*y; else acc1 += g[s]*y;
  }
  d_fea2[b*D2 + o] = acc0;
  d_fea2[(size_t)NB*D2 + b*D2 + o] = acc1;
}

__global__ void normrelu_kernel(int mode){
  int i = blockIdx.x*blockDim.x + threadIdx.x;
  if(mode==0){
    if(i >= 2*NB*128) return;
    int o = i & 127; int t = i / (NB*128);
    d_t1[i] = fmaxf(d_t1raw[i]*d_aT0[t*128+o] + d_cT0[t*128+o], 0.f);
  } else {
    if(i >= 2*NB*64) return;
    int o = i & 63; int t = i / (NB*64);
    d_t2[i] = fmaxf(d_t2raw[i]*d_aT1[t*64+o] + d_cT1[t*64+o], 0.f);
  }
}

__global__ void final_kernel(const float* __restrict__ tow, const float* __restrict__ tob,
                             float* __restrict__ out){
  int w = (blockIdx.x*blockDim.x + threadIdx.x) >> 5;
  int lane = threadIdx.x & 31;
  if(w >= NB) return;
  size_t b = (size_t)w;
  float s0 = d_t2[b*64 + lane]*tow[lane] + d_t2[b*64 + lane + 32]*tow[lane + 32];
  float s1 = d_t2[(size_t)NB*64 + b*64 + lane]*tow[64 + lane]
           + d_t2[(size_t)NB*64 + b*64 + lane + 32]*tow[64 + lane + 32];
  #pragma unroll
  for(int off=16; off; off>>=1){
    s0 += __shfl_xor_sync(0xffffffffu, s0, off);
    s1 += __shfl_xor_sync(0xffffffffu, s1, off);
  }
  if(lane==0){
    out[b]      = 1.f/(1.f + expf(-(s0 + tob[0])));
    out[NB + b] = 1.f/(1.f + expf(-(s1 + tob[1])));
  }
}

// ---------------- host launcher ----------------
extern "C" void kernel_launch(void* const* d_in, const int* in_sizes, int n_in,
                              void* d_out, int out_size){
  const int*   x    = (const int*)  d_in[0];
  const float* emb  = (const float*)d_in[1];
  const float* ew0  = (const float*)d_in[2];
  const float* eg0  = (const float*)d_in[4];
  const float* ebt0 = (const float*)d_in[5];
  const float* gw0  = (const float*)d_in[6];
  const float* gb0  = (const float*)d_in[7];
  const float* ew1  = (const float*)d_in[10];
  const float* eg1  = (const float*)d_in[12];
  const float* ebt1 = (const float*)d_in[13];
  const float* gw1  = (const float*)d_in[14];
  const float* gb1  = (const float*)d_in[15];
  const float* tw0  = (const float*)d_in[18];
  const float* tg0  = (const float*)d_in[20];
  const float* tbt0 = (const float*)d_in[21];
  const float* tw1  = (const float*)d_in[22];
  const float* tg1  = (const float*)d_in[24];
  const float* tbt1 = (const float*)d_in[25];
  const float* tow  = (const float*)d_in[26];
  const float* tob  = (const float*)d_in[27];
  float* out = (float*)d_out;

  static bool attr_set = false;
  if(!attr_set){
    cudaFuncSetAttribute(bf16_gemm_kernel, cudaFuncAttributeMaxDynamicSharedMemorySize, SMEM_GB);
    attr_set = true;
  }

  __nv_bfloat16* w0b; cudaGetSymbolAddress((void**)&w0b, d_w0b);
  __nv_bfloat16* w1b; cudaGetSymbolAddress((void**)&w1b, d_w1b);

  zero_stats_kernel<<<(12*D1 + 255)/256, 256>>>();
  conv_bf16_kernel<<<(12*IN0*D1 + 255)/256, 256>>>(ew0, w0b, 12*IN0*D1);
  conv_bf16_kernel<<<(12*D1*D2 + 255)/256, 256>>>(ew1, w1b, 12*D1*D2);
  gather_kernel<<<(NB*NF*NE)/256, 256>>>(x, emb);
  gate0_kernel<<<(NB*32)/256, 256>>>(gw0, gb0);

  bf16_gemm_kernel<<<dim3(D1/BN, NB/BM, 12), 256, SMEM_GB>>>(0, w0b, w1b);
  finalize_kernel<<<(12*D1 + 255)/256, 256>>>(0, eg0, ebt0);
  combine0_kernel<<<(NB*D1)/256, 256>>>();

  gate1_kernel<<<(NB*32)/256, 256>>>(gw1, gb1);
  bf16_gemm_kernel<<<dim3(D2/BN, NB/BM, 16), 256, SMEM_GB>>>(1, w0b, w1b);
  finalize_kernel<<<(16*D2 + 255)/256, 256>>>(1, eg1, ebt1);
  combine1_kernel<<<(NB*D2)/256, 256>>>();

  sgemm_kernel<<<dim3(1, NB/128, 2), 256>>>(2, tw0);
  finalize_kernel<<<1, 256>>>(2, tg0, tbt0);
  normrelu_kernel<<<(2*NB*128)/256, 256>>>(0);

  sgemm_kernel<<<dim3(1, NB/128, 2), 256>>>(3, tw1);
  finalize_kernel<<<1, 256>>>(3, tg1, tbt1);
  normrelu_kernel<<<(2*NB*64)/256, 256>>>(1);

  final_kernel<<<(NB*32)/256, 256>>>(tow, tob, out);
}

// round 6
// speedup vs baseline: 4.2594x; 1.0446x over previous
#include <cuda_runtime.h>
#include <cuda_bf16.h>
#include <mma.h>
#include <math.h>
#include <stdint.h>

using namespace nvcuda;

// Problem constants
constexpr int NB   = 16384;
constexpr int NF   = 18;
constexpr int NE   = 64;
constexpr int IN0  = 1152;
constexpr int D1   = 512;
constexpr int D2   = 256;
constexpr int NVOC = 100000;

// ---------------- static device scratch ----------------
__device__ __align__(1024) float d_feat [(size_t)NB*IN0];           // f32 (gates)
__device__ __align__(1024) __nv_bfloat16 d_featb[(size_t)NB*IN0];   // bf16 (MMA)
__device__ __align__(1024) float d_h0   [(size_t)12*NB*D1];
__device__ __align__(1024) float d_h1   [(size_t)16*NB*D2];
__device__ __align__(1024) float d_fea1 [(size_t)2*NB*D1];          // f32 (gate1)
__device__ __align__(1024) __nv_bfloat16 d_fea1b[(size_t)2*NB*D1];  // bf16 (MMA)
__device__ __align__(1024) float d_fea2 [(size_t)2*NB*D2];
__device__ __align__(1024) __nv_bfloat16 d_w0b[(size_t)12*IN0*D1];
__device__ __align__(1024) __nv_bfloat16 d_w1b[(size_t)12*D1*D2];
__device__ float d_t1raw[(size_t)2*NB*128];
__device__ float d_t1   [(size_t)2*NB*128];
__device__ float d_t2raw[(size_t)2*NB*64];
__device__ float d_t2   [(size_t)2*NB*64];
__device__ float d_gate0[(size_t)NB*16];
__device__ float d_gate1[(size_t)NB*16];

__device__ float d_sum0[12*D1], d_sq0[12*D1], d_a0[12*D1], d_c0[12*D1];
__device__ float d_sum1[16*D2], d_sq1[16*D2], d_a1[16*D2], d_c1[16*D2];
__device__ float d_sumT0[2*128], d_sqT0[2*128], d_aT0[2*128], d_cT0[2*128];
__device__ float d_sumT1[2*64],  d_sqT1[2*64],  d_aT1[2*64],  d_cT1[2*64];

__device__ __forceinline__ int expert_of(int z){
  int t = z >> 3, k = z & 7;
  return (k < 4) ? (t*4 + k) : (4 + k);
}

// ---------------- cp.async helpers ----------------
__device__ __forceinline__ uint32_t smem_u32(const void* p){
  uint32_t a;
  asm("{ .reg .u64 t; cvta.to.shared.u64 t, %1; cvt.u32.u64 %0, t; }" : "=r"(a) : "l"(p));
  return a;
}
__device__ __forceinline__ void cp16(uint32_t s, const void* g){
  asm volatile("cp.async.cg.shared.global [%0], [%1], 16;" :: "r"(s), "l"(g) : "memory");
}
#define CP_COMMIT() asm volatile("cp.async.commit_group;" ::: "memory")
#define CP_WAIT(n)  asm volatile("cp.async.wait_group %0;" :: "n"(n) : "memory")

// ---------------- bf16 wmma grouped GEMM, 3-stage pipeline, fused BN stats ----
constexpr int BM = 128, BN = 128, BKb = 64;
constexpr int S_STG = 3;
constexpr int A_LDb = 72;                      // bf16 per A smem row (64+8 pad)
constexpr int B_LDb = 136;                     // bf16 per B smem row (128+8 pad)
constexpr int A_STG_B = BM * A_LDb * 2;        // 18432 bytes
constexpr int B_STG_B = BKb * B_LDb * 2;       // 17408 bytes
constexpr int STG_B   = A_STG_B + B_STG_B;     // 35840
constexpr int PIPE_B  = S_STG * STG_B;         // 107520
constexpr int EPI_B   = 128 * 132 * 4;         // 67584
constexpr int SMEM_GB = (PIPE_B > EPI_B) ? PIPE_B : EPI_B;   // 107520

typedef wmma::fragment<wmma::matrix_a, 16,16,16, __nv_bfloat16, wmma::row_major> FA;
typedef wmma::fragment<wmma::matrix_b, 16,16,16, __nv_bfloat16, wmma::row_major> FB;
typedef wmma::fragment<wmma::accumulator, 16,16,16, float> FC;

__global__ void __launch_bounds__(256,2) bf16_gemm_kernel(int mode,
                                                          const __nv_bfloat16* __restrict__ w0,
                                                          const __nv_bfloat16* __restrict__ w1){
  extern __shared__ char sm[];
  const uint32_t sb = smem_u32(sm);
  const int tid = threadIdx.x;
  const int wid = tid >> 5;
  const int wm = wid >> 2;     // 0..1 -> 64-row slice
  const int wn = wid & 3;      // 0..3 -> 32-col slice

  const int z = blockIdx.z;
  const __nv_bfloat16* A; const __nv_bfloat16* W; float* C; float* sumP; float* sqP;
  int N, K;
  if(mode == 0){
    A = d_featb; K = IN0; N = D1;
    W = w0 + (size_t)z*K*N;
    C = d_h0 + (size_t)z*NB*N;
    sumP = d_sum0 + z*N; sqP = d_sq0 + z*N;
  } else {
    int t = z >> 3, e = expert_of(z);
    A = d_fea1b + (size_t)t*NB*D1; K = D1; N = D2;
    W = w1 + (size_t)e*K*N;
    C = d_h1 + (size_t)z*NB*N;
    sumP = d_sum1 + z*N; sqP = d_sq1 + z*N;
  }
  const int NK = K / BKb;
  const int m0 = blockIdx.y * BM;
  const int n0 = blockIdx.x * BN;

  const __nv_bfloat16* Abase = A + (size_t)m0 * K;
  const __nv_bfloat16* Bbase = W + n0;

  auto load_stage = [&](int kc, int buf){
    const __nv_bfloat16* gA = Abase + (size_t)kc * BKb;
    const __nv_bfloat16* gB = Bbase + (size_t)kc * BKb * N;
    uint32_t sA = sb + buf * STG_B;
    uint32_t sB = sA + A_STG_B;
    #pragma unroll
    for(int it = 0; it < 4; ++it){
      int idx = it*256 + tid;
      int r = idx >> 3, q = idx & 7;
      cp16(sA + (uint32_t)(r*A_LDb + q*8)*2, gA + (size_t)r*K + q*8);
    }
    #pragma unroll
    for(int it = 0; it < 4; ++it){
      int idx = it*256 + tid;
      int r = idx >> 4, q = idx & 15;
      cp16(sB + (uint32_t)(r*B_LDb + q*8)*2, gB + (size_t)r*N + q*8);
    }
  };

  FC acc[4][2];
  #pragma unroll
  for(int i = 0; i < 4; ++i)
    #pragma unroll
    for(int j = 0; j < 2; ++j) wmma::fill_fragment(acc[i][j], 0.f);

  // prologue: stages 0,1 in flight
  load_stage(0, 0); CP_COMMIT();
  load_stage(1, 1); CP_COMMIT();

  for(int kc = 0; kc < NK; ++kc){
    CP_WAIT(1);               // stage kc resident
    __syncthreads();          // all warps past iter kc-1 -> buffer (kc+2)%3 free
    int ts = kc + 2;
    if(ts < NK) load_stage(ts, ts % S_STG);
    CP_COMMIT();
    const __nv_bfloat16* As = (const __nv_bfloat16*)(sm + (kc % S_STG) * STG_B);
    const __nv_bfloat16* Bs = (const __nv_bfloat16*)(sm + (kc % S_STG) * STG_B + A_STG_B);
    #pragma unroll
    for(int ks = 0; ks < 4; ++ks){
      FB b0, b1;
      wmma::load_matrix_sync(b0, Bs + (ks*16)*B_LDb + wn*32, B_LDb);
      wmma::load_matrix_sync(b1, Bs + (ks*16)*B_LDb + wn*32 + 16, B_LDb);
      #pragma unroll
      for(int im = 0; im < 4; ++im){
        FA a;
        wmma::load_matrix_sync(a, As + (wm*64 + im*16)*A_LDb + ks*16, A_LDb);
        wmma::mma_sync(acc[im][0], a, b0, acc[im][0]);
        wmma::mma_sync(acc[im][1], a, b1, acc[im][1]);
      }
    }
  }
  __syncthreads();   // pipeline smem dead; safe to reuse for epilogue

  // ---- epilogue: frags -> smem(f32) -> coalesced gmem + fused BN stats ----
  float* shf = (float*)sm;     // 128 x 132
  #pragma unroll
  for(int im = 0; im < 4; ++im)
    #pragma unroll
    for(int jn = 0; jn < 2; ++jn)
      wmma::store_matrix_sync(shf + (wm*64 + im*16)*132 + wn*32 + jn*16,
                              acc[im][jn], 132, wmma::mem_row_major);
  __syncthreads();

  float* Crow = C + (size_t)m0*N + n0;
  #pragma unroll 4
  for(int it = 0; it < 16; ++it){
    int idx = it*256 + tid;
    int row = idx >> 5, q = (idx & 31)*4;
    float4 v = make_float4(shf[row*132+q], shf[row*132+q+1],
                           shf[row*132+q+2], shf[row*132+q+3]);
    *(float4*)(Crow + (size_t)row*N + q) = v;
  }
  {
    int col = tid & 127, half = tid >> 7;
    float s = 0.f, q = 0.f;
    #pragma unroll 8
    for(int r = half*64; r < half*64 + 64; ++r){
      float v = shf[r*132 + col]; s += v; q += v*v;
    }
    atomicAdd(&sumP[n0 + col], s);
    atomicAdd(&sqP[n0 + col], q);
  }
}

// f32 -> bf16 conversion (weights), float4-vectorized
__global__ void conv_bf16_kernel(const float* __restrict__ src, __nv_bfloat16* __restrict__ dst, int n4){
  int i = blockIdx.x*blockDim.x + threadIdx.x;
  if(i >= n4) return;
  float4 v = *(const float4*)(src + (size_t)i*4);
  __nv_bfloat162 lo = __floats2bfloat162_rn(v.x, v.y);
  __nv_bfloat162 hi = __floats2bfloat162_rn(v.z, v.w);
  uint2 pk; pk.x = *(unsigned*)&lo; pk.y = *(unsigned*)&hi;
  *(uint2*)(dst + (size_t)i*4) = pk;
}

// ---------------- small kernels ----------------
__global__ void zero_stats_kernel(){
  int i = blockIdx.x*blockDim.x + threadIdx.x;
  if(i < 12*D1){ d_sum0[i]=0.f; d_sq0[i]=0.f; }
  if(i < 16*D2){ d_sum1[i]=0.f; d_sq1[i]=0.f; }
  if(i < 2*128){ d_sumT0[i]=0.f; d_sqT0[i]=0.f; }
  if(i < 2*64 ){ d_sumT1[i]=0.f; d_sqT1[i]=0.f; }
}

// float4 gather: 1 thread = 4 embedding elems; writes f32 + packed bf16
__global__ void gather_kernel(const int* __restrict__ x, const float* __restrict__ emb){
  int idx = blockIdx.x*blockDim.x + threadIdx.x;   // NB*NF*16
  int q = idx & 15;
  int f = (idx >> 4) % NF;
  int b = idx / (16*NF);
  int v = x[b*NF + f];
  float4 val = *(const float4*)(emb + ((size_t)f*NVOC + (size_t)v)*NE + q*4);
  *(float4*)(d_feat + (size_t)b*IN0 + f*NE + q*4) = val;
  __nv_bfloat162 lo = __floats2bfloat162_rn(val.x, val.y);
  __nv_bfloat162 hi = __floats2bfloat162_rn(val.z, val.w);
  uint2 pk; pk.x = *(unsigned*)&lo; pk.y = *(unsigned*)&hi;
  *(uint2*)(d_featb + (size_t)b*IN0 + f*NE + q*4) = pk;
}

__device__ __forceinline__ void warp_reduce16(float* acc){
  #pragma unroll
  for(int off=16; off; off>>=1)
    #pragma unroll
    for(int j=0;j<16;j++) acc[j] += __shfl_xor_sync(0xffffffffu, acc[j], off);
}
__device__ __forceinline__ void softmax8(const float* l, float* o){
  float m = l[0];
  #pragma unroll
  for(int j=1;j<8;j++) m = fmaxf(m, l[j]);
  float s = 0.f, e[8];
  #pragma unroll
  for(int j=0;j<8;j++){ e[j] = expf(l[j]-m); s += e[j]; }
  float inv = 1.f/s;
  #pragma unroll
  for(int j=0;j<8;j++) o[j] = e[j]*inv;
}

__global__ void gate0_kernel(const float* __restrict__ gw, const float* __restrict__ gb){
  int w = (blockIdx.x*blockDim.x + threadIdx.x) >> 5;
  int lane = threadIdx.x & 31;
  if(w >= NB) return;
  const float* frow = d_feat + (size_t)w*IN0;
  float acc[16];
  #pragma unroll
  for(int j=0;j<16;j++) acc[j]=0.f;
  for(int k=lane;k<IN0;k+=32){
    float fv = frow[k];
    const float* g0 = gw + k*8;
    const float* g1 = gw + IN0*8 + k*8;
    #pragma unroll
    for(int j=0;j<8;j++){ acc[j] += fv*g0[j]; acc[8+j] += fv*g1[j]; }
  }
  warp_reduce16(acc);
  if(lane==0){
    float l[8], o[8];
    #pragma unroll
    for(int t=0;t<2;t++){
      #pragma unroll
      for(int j=0;j<8;j++) l[j] = acc[t*8+j] + gb[t*8+j];
      softmax8(l,o);
      #pragma unroll
      for(int j=0;j<8;j++) d_gate0[(size_t)w*16 + t*8 + j] = o[j];
    }
  }
}

__global__ void gate1_kernel(const float* __restrict__ gw, const float* __restrict__ gb){
  int w = (blockIdx.x*blockDim.x + threadIdx.x) >> 5;
  int lane = threadIdx.x & 31;
  if(w >= NB) return;
  const float* f0 = d_fea1 + (size_t)w*D1;
  const float* f1 = d_fea1 + (size_t)NB*D1 + (size_t)w*D1;
  float acc[16];
  #pragma unroll
  for(int j=0;j<16;j++) acc[j]=0.f;
  for(int k=lane;k<D1;k+=32){
    float v0 = f0[k], v1 = f1[k];
    const float* g0 = gw + k*8;
    const float* g1 = gw + D1*8 + k*8;
    #pragma unroll
    for(int j=0;j<8;j++){ acc[j] += v0*g0[j]; acc[8+j] += v1*g1[j]; }
  }
  warp_reduce16(acc);
  if(lane==0){
    float l[8], o[8];
    #pragma unroll
    for(int t=0;t<2;t++){
      #pragma unroll
      for(int j=0;j<8;j++) l[j] = acc[t*8+j] + gb[t*8+j];
      softmax8(l,o);
      #pragma unroll
      for(int j=0;j<8;j++) d_gate1[(size_t)w*16 + t*8 + j] = o[j];
    }
  }
}

// SIMT SGEMM for the small tower layers: mode 2 / mode 3 (fused stats).
__global__ void __launch_bounds__(256,2) sgemm_kernel(int mode, const float* __restrict__ w_base){
  __shared__ float sh[2048];
  float* As = sh;
  float* Bs = sh + 1024;

  const int z = blockIdx.z;
  const float* A; const float* W; float* C; float* sumP; float* sqP;
  int N, K;
  if(mode==2){
    A=d_fea2 + (size_t)z*NB*D2; K=D2; N=128;
    W=w_base + (size_t)z*K*N; C=d_t1raw + (size_t)z*NB*N;
    sumP=d_sumT0 + z*N; sqP=d_sqT0 + z*N;
  } else {
    A=d_t1 + (size_t)z*NB*128; K=128; N=64;
    W=w_base + (size_t)z*K*N; C=d_t2raw + (size_t)z*NB*N;
    sumP=d_sumT1 + z*N; sqP=d_sqT1 + z*N;
  }

  const int tid = threadIdx.x;
  const int tx = tid & 15, ty = tid >> 4;
  const int m0 = blockIdx.y*128, n0 = blockIdx.x*128;
  const int arow = tid >> 1, acol = (tid & 1)*4;
  const int brow = tid >> 5, bcol = (tid & 31)*4;

  float acc[8][8];
  #pragma unroll
  for(int i=0;i<8;i++)
    #pragma unroll
    for(int j=0;j<8;j++) acc[i][j]=0.f;

  const float* Aptr = A + (size_t)(m0+arow)*K + acol;
  const bool bload = (n0 + bcol) < N;

  for(int k0=0; k0<K; k0+=8){
    float4 av = *(const float4*)(Aptr + k0);
    As[(acol+0)*128 + arow] = av.x;
    As[(acol+1)*128 + arow] = av.y;
    As[(acol+2)*128 + arow] = av.z;
    As[(acol+3)*128 + arow] = av.w;
    float4 bv = bload ? *(const float4*)(W + (size_t)(k0+brow)*N + n0 + bcol)
                      : make_float4(0.f,0.f,0.f,0.f);
    *(float4*)(Bs + brow*128 + bcol) = bv;
    __syncthreads();
    #pragma unroll
    for(int kk=0;kk<8;kk++){
      float a[8], bb[8];
      *(float4*)(a)    = *(float4*)(As + kk*128 + ty*8);
      *(float4*)(a+4)  = *(float4*)(As + kk*128 + ty*8 + 4);
      *(float4*)(bb)   = *(float4*)(Bs + kk*128 + tx*8);
      *(float4*)(bb+4) = *(float4*)(Bs + kk*128 + tx*8 + 4);
      #pragma unroll
      for(int i=0;i<8;i++)
        #pragma unroll
        for(int j=0;j<8;j++) acc[i][j] += a[i]*bb[j];
    }
    __syncthreads();
  }

  float s1[8], s2[8];
  #pragma unroll
  for(int j=0;j<8;j++){ s1[j]=0.f; s2[j]=0.f; }
  const bool wok = (n0 + tx*8) < N;
  #pragma unroll
  for(int i=0;i<8;i++){
    int m = m0 + ty*8 + i;
    #pragma unroll
    for(int j=0;j<8;j++){ float v = acc[i][j]; s1[j]+=v; s2[j]+=v*v; }
    if(wok){
      *(float4*)(C + (size_t)m*N + n0 + tx*8)     = *(float4*)&acc[i][0];
      *(float4*)(C + (size_t)m*N + n0 + tx*8 + 4) = *(float4*)&acc[i][4];
    }
  }
  __syncthreads();
  #pragma unroll
  for(int j=0;j<8;j++) sh[ty*128 + tx*8 + j] = s1[j];
  __syncthreads();
  if(tid < 128 && (n0 + tid) < N){
    float t = 0.f;
    #pragma unroll
    for(int r=0;r<16;r++) t += sh[r*128 + tid];
    atomicAdd(&sumP[n0 + tid], t);
  }
  __syncthreads();
  #pragma unroll
  for(int j=0;j<8;j++) sh[ty*128 + tx*8 + j] = s2[j];
  __syncthreads();
  if(tid < 128 && (n0 + tid) < N){
    float t = 0.f;
    #pragma unroll
    for(int r=0;r<16;r++) t += sh[r*128 + tid];
    atomicAdd(&sqP[n0 + tid], t);
  }
}

__global__ void finalize_kernel(int mode, const float* __restrict__ g, const float* __restrict__ bt){
  int i = blockIdx.x*blockDim.x + threadIdx.x;
  const float* sum; const float* sq; float* a; float* c; int N, NZ;
  if(mode==0){ sum=d_sum0; sq=d_sq0; a=d_a0; c=d_c0; N=D1; NZ=12; }
  else if(mode==1){ sum=d_sum1; sq=d_sq1; a=d_a1; c=d_c1; N=D2; NZ=16; }
  else if(mode==2){ sum=d_sumT0; sq=d_sqT0; a=d_aT0; c=d_cT0; N=128; NZ=2; }
  else { sum=d_sumT1; sq=d_sqT1; a=d_aT1; c=d_cT1; N=64; NZ=2; }
  if(i >= NZ*N) return;
  int z = i / N, o = i - z*N;
  int gz = (mode==1) ? expert_of(z) : z;
  float mu  = sum[i] * (1.f/NB);
  float var = sq[i] * (1.f/NB) - mu*mu;
  float aa  = g[gz*N+o] * rsqrtf(var + 1e-5f);
  a[i] = aa;
  c[i] = bt[gz*N+o] - mu*aa;
}

// float4 combine: BN+relu per expert, gate-weighted sums, writes f32 + bf16
__global__ void combine0_kernel(){
  int idx = blockIdx.x*blockDim.x + threadIdx.x;   // NB*128
  int o4 = (idx & 127)*4;
  size_t b = (size_t)(idx >> 7);
  const float* g = d_gate0 + b*16;
  float4 acc0 = make_float4(0,0,0,0), acc1 = make_float4(0,0,0,0);
  #pragma unroll
  for(int e=0;e<12;e++){
    float4 h = *(const float4*)(d_h0 + ((size_t)e*NB + b)*D1 + o4);
    float4 a = *(const float4*)(d_a0 + e*D1 + o4);
    float4 c = *(const float4*)(d_c0 + e*D1 + o4);
    float4 y;
    y.x = fmaxf(h.x*a.x + c.x, 0.f);
    y.y = fmaxf(h.y*a.y + c.y, 0.f);
    y.z = fmaxf(h.z*a.z + c.z, 0.f);
    y.w = fmaxf(h.w*a.w + c.w, 0.f);
    float g0 = (e < 4) ? g[e] : ((e >= 8) ? g[e-4] : 0.f);
    float g1 = (e >= 4) ? g[8 + e - 4] : 0.f;
    acc0.x += g0*y.x; acc0.y += g0*y.y; acc0.z += g0*y.z; acc0.w += g0*y.w;
    acc1.x += g1*y.x; acc1.y += g1*y.y; acc1.z += g1*y.z; acc1.w += g1*y.w;
  }
  *(float4*)(d_fea1 + b*D1 + o4) = acc0;
  *(float4*)(d_fea1 + (size_t)NB*D1 + b*D1 + o4) = acc1;
  __nv_bfloat162 l0 = __floats2bfloat162_rn(acc0.x, acc0.y);
  __nv_bfloat162 h0 = __floats2bfloat162_rn(acc0.z, acc0.w);
  uint2 p0; p0.x = *(unsigned*)&l0; p0.y = *(unsigned*)&h0;
  *(uint2*)(d_fea1b + b*D1 + o4) = p0;
  __nv_bfloat162 l1 = __floats2bfloat162_rn(acc1.x, acc1.y);
  __nv_bfloat162 h1 = __floats2bfloat162_rn(acc1.z, acc1.w);
  uint2 p1; p1.x = *(unsigned*)&l1; p1.y = *(unsigned*)&h1;
  *(uint2*)(d_fea1b + (size_t)NB*D1 + b*D1 + o4) = p1;
}

__global__ void combine1_kernel(){
  int idx = blockIdx.x*blockDim.x + threadIdx.x;   // NB*64
  int o4 = (idx & 63)*4;
  size_t b = (size_t)(idx >> 6);
  const float* g = d_gate1 + b*16;
  float4 acc0 = make_float4(0,0,0,0), acc1 = make_float4(0,0,0,0);
  #pragma unroll
  for(int s=0;s<16;s++){
    float4 h = *(const float4*)(d_h1 + ((size_t)s*NB + b)*D2 + o4);
    float4 a = *(const float4*)(d_a1 + s*D2 + o4);
    float4 c = *(const float4*)(d_c1 + s*D2 + o4);
    float4 y;
    y.x = fmaxf(h.x*a.x + c.x, 0.f);
    y.y = fmaxf(h.y*a.y + c.y, 0.f);
    y.z = fmaxf(h.z*a.z + c.z, 0.f);
    y.w = fmaxf(h.w*a.w + c.w, 0.f);
    float gv = g[s];
    if(s < 8){ acc0.x += gv*y.x; acc0.y += gv*y.y; acc0.z += gv*y.z; acc0.w += gv*y.w; }
    else     { acc1.x += gv*y.x; acc1.y += gv*y.y; acc1.z += gv*y.z; acc1.w += gv*y.w; }
  }
  *(float4*)(d_fea2 + b*D2 + o4) = acc0;
  *(float4*)(d_fea2 + (size_t)NB*D2 + b*D2 + o4) = acc1;
}

__global__ void normrelu_kernel(int mode){
  int i = blockIdx.x*blockDim.x + threadIdx.x;
  if(mode==0){
    if(i >= 2*NB*128) return;
    int o = i & 127; int t = i / (NB*128);
    d_t1[i] = fmaxf(d_t1raw[i]*d_aT0[t*128+o] + d_cT0[t*128+o], 0.f);
  } else {
    if(i >= 2*NB*64) return;
    int o = i & 63; int t = i / (NB*64);
    d_t2[i] = fmaxf(d_t2raw[i]*d_aT1[t*64+o] + d_cT1[t*64+o], 0.f);
  }
}

__global__ void final_kernel(const float* __restrict__ tow, const float* __restrict__ tob,
                             float* __restrict__ out){
  int w = (blockIdx.x*blockDim.x + threadIdx.x) >> 5;
  int lane = threadIdx.x & 31;
  if(w >= NB) return;
  size_t b = (size_t)w;
  float s0 = d_t2[b*64 + lane]*tow[lane] + d_t2[b*64 + lane + 32]*tow[lane + 32];
  float s1 = d_t2[(size_t)NB*64 + b*64 + lane]*tow[64 + lane]
           + d_t2[(size_t)NB*64 + b*64 + lane + 32]*tow[64 + lane + 32];
  #pragma unroll
  for(int off=16; off; off>>=1){
    s0 += __shfl_xor_sync(0xffffffffu, s0, off);
    s1 += __shfl_xor_sync(0xffffffffu, s1, off);
  }
  if(lane==0){
    out[b]      = 1.f/(1.f + expf(-(s0 + tob[0])));
    out[NB + b] = 1.f/(1.f + expf(-(s1 + tob[1])));
  }
}

// ---------------- host launcher ----------------
extern "C" void kernel_launch(void* const* d_in, const int* in_sizes, int n_in,
                              void* d_out, int out_size){
  const int*   x    = (const int*)  d_in[0];
  const float* emb  = (const float*)d_in[1];
  const float* ew0  = (const float*)d_in[2];
  const float* eg0  = (const float*)d_in[4];
  const float* ebt0 = (const float*)d_in[5];
  const float* gw0  = (const float*)d_in[6];
  const float* gb0  = (const float*)d_in[7];
  const float* ew1  = (const float*)d_in[10];
  const float* eg1  = (const float*)d_in[12];
  const float* ebt1 = (const float*)d_in[13];
  const float* gw1  = (const float*)d_in[14];
  const float* gb1  = (const float*)d_in[15];
  const float* tw0  = (const float*)d_in[18];
  const float* tg0  = (const float*)d_in[20];
  const float* tbt0 = (const float*)d_in[21];
  const float* tw1  = (const float*)d_in[22];
  const float* tg1  = (const float*)d_in[24];
  const float* tbt1 = (const float*)d_in[25];
  const float* tow  = (const float*)d_in[26];
  const float* tob  = (const float*)d_in[27];
  float* out = (float*)d_out;

  static bool attr_set = false;
  if(!attr_set){
    cudaFuncSetAttribute(bf16_gemm_kernel, cudaFuncAttributeMaxDynamicSharedMemorySize, SMEM_GB);
    attr_set = true;
  }

  __nv_bfloat16* w0b; cudaGetSymbolAddress((void**)&w0b, d_w0b);
  __nv_bfloat16* w1b; cudaGetSymbolAddress((void**)&w1b, d_w1b);

  zero_stats_kernel<<<(12*D1 + 255)/256, 256>>>();
  conv_bf16_kernel<<<(12*IN0*D1/4 + 255)/256, 256>>>(ew0, w0b, 12*IN0*D1/4);
  conv_bf16_kernel<<<(12*D1*D2/4 + 255)/256, 256>>>(ew1, w1b, 12*D1*D2/4);
  gather_kernel<<<(NB*NF*16)/256, 256>>>(x, emb);
  gate0_kernel<<<(NB*32)/256, 256>>>(gw0, gb0);

  bf16_gemm_kernel<<<dim3(D1/BN, NB/BM, 12), 256, SMEM_GB>>>(0, w0b, w1b);
  finalize_kernel<<<(12*D1 + 255)/256, 256>>>(0, eg0, ebt0);
  combine0_kernel<<<(NB*128)/256, 256>>>();

  gate1_kernel<<<(NB*32)/256, 256>>>(gw1, gb1);
  bf16_gemm_kernel<<<dim3(D2/BN, NB/BM, 16), 256, SMEM_GB>>>(1, w0b, w1b);
  finalize_kernel<<<(16*D2 + 255)/256, 256>>>(1, eg1, ebt1);
  combine1_kernel<<<(NB*64)/256, 256>>>();

  sgemm_kernel<<<dim3(1, NB/128, 2), 256>>>(2, tw0);
  finalize_kernel<<<1, 256>>>(2, tg0, tbt0);
  normrelu_kernel<<<(2*NB*128)/256, 256>>>(0);

  sgemm_kernel<<<dim3(1, NB/128, 2), 256>>>(3, tw1);
  finalize_kernel<<<1, 256>>>(3, tg1, tbt1);
  normrelu_kernel<<<(2*NB*64)/256, 256>>>(1);

  final_kernel<<<(NB*32)/256, 256>>>(tow, tob, out);
}

// round 7
// speedup vs baseline: 4.4767x; 1.0510x over previous
#include <cuda_runtime.h>
#include <cuda_bf16.h>
#include <mma.h>
#include <math.h>
#include <stdint.h>

using namespace nvcuda;

// Problem constants
constexpr int NB   = 16384;
constexpr int NF   = 18;
constexpr int NE   = 64;
constexpr int IN0  = 1152;
constexpr int D1   = 512;
constexpr int D2   = 256;
constexpr int NVOC = 100000;

// ---------------- static device scratch ----------------
__device__ __align__(1024) float d_feat [(size_t)NB*IN0];           // f32 (gates)
__device__ __align__(1024) __nv_bfloat16 d_featb[(size_t)NB*IN0];   // bf16 (MMA)
__device__ __align__(1024) float d_h0   [(size_t)12*NB*D1];
__device__ __align__(1024) float d_h1   [(size_t)16*NB*D2];
__device__ __align__(1024) float d_fea1 [(size_t)2*NB*D1];          // f32 (gate1)
__device__ __align__(1024) __nv_bfloat16 d_fea1b[(size_t)2*NB*D1];  // bf16 (MMA)
__device__ __align__(1024) float d_fea2 [(size_t)2*NB*D2];
__device__ __align__(1024) __nv_bfloat16 d_w0b[(size_t)12*IN0*D1];
__device__ __align__(1024) __nv_bfloat16 d_w1b[(size_t)12*D1*D2];
__device__ float d_t1raw[(size_t)2*NB*128];
__device__ float d_t1   [(size_t)2*NB*128];
__device__ float d_t2raw[(size_t)2*NB*64];
__device__ float d_t2   [(size_t)2*NB*64];
__device__ float d_gate0[(size_t)NB*16];
__device__ float d_gate1[(size_t)NB*16];

__device__ float d_sum0[12*D1], d_sq0[12*D1], d_a0[12*D1], d_c0[12*D1];
__device__ float d_sum1[16*D2], d_sq1[16*D2], d_a1[16*D2], d_c1[16*D2];
__device__ float d_sumT0[2*128], d_sqT0[2*128], d_aT0[2*128], d_cT0[2*128];
__device__ float d_sumT1[2*64],  d_sqT1[2*64],  d_aT1[2*64],  d_cT1[2*64];

__device__ __forceinline__ int expert_of(int z){
  int t = z >> 3, k = z & 7;
  return (k < 4) ? (t*4 + k) : (4 + k);
}

// ---------------- cp.async helpers ----------------
__device__ __forceinline__ uint32_t smem_u32(const void* p){
  uint32_t a;
  asm("{ .reg .u64 t; cvta.to.shared.u64 t, %1; cvt.u32.u64 %0, t; }" : "=r"(a) : "l"(p));
  return a;
}
__device__ __forceinline__ void cp16(uint32_t s, const void* g){
  asm volatile("cp.async.cg.shared.global [%0], [%1], 16;" :: "r"(s), "l"(g) : "memory");
}
#define CP_COMMIT() asm volatile("cp.async.commit_group;" ::: "memory")
#define CP_WAIT(n)  asm volatile("cp.async.wait_group %0;" :: "n"(n) : "memory")

// ---------------- bf16 wmma grouped GEMM ----------------
// 128 threads (4 warps, 2x2), warp tile 64x64, CTA tile 128x128, BK=64,
// 3-stage cp.async pipeline, fused BN stats epilogue.
constexpr int BM = 128, BN = 128, BKb = 64;
constexpr int S_STG = 3;
constexpr int A_LDb = 72;                      // bf16 per A smem row (64+8 pad)
constexpr int B_LDb = 136;                     // bf16 per B smem row (128+8 pad)
constexpr int A_STG_B = BM * A_LDb * 2;        // 18432 bytes
constexpr int B_STG_B = BKb * B_LDb * 2;       // 17408 bytes
constexpr int STG_B   = A_STG_B + B_STG_B;     // 35840
constexpr int PIPE_B  = S_STG * STG_B;         // 107520
constexpr int EPI_B   = 128 * 132 * 4;         // 67584
constexpr int SMEM_GB = (PIPE_B > EPI_B) ? PIPE_B : EPI_B;   // 107520

typedef wmma::fragment<wmma::matrix_a, 16,16,16, __nv_bfloat16, wmma::row_major> FA;
typedef wmma::fragment<wmma::matrix_b, 16,16,16, __nv_bfloat16, wmma::row_major> FB;
typedef wmma::fragment<wmma::accumulator, 16,16,16, float> FC;

__global__ void __launch_bounds__(128,2) bf16_gemm_kernel(int mode,
                                                          const __nv_bfloat16* __restrict__ w0,
                                                          const __nv_bfloat16* __restrict__ w1){
  extern __shared__ char sm[];
  const uint32_t sb = smem_u32(sm);
  const int tid = threadIdx.x;
  const int wid = tid >> 5;
  const int wm = wid >> 1;     // 0..1 -> 64-row slice
  const int wn = wid & 1;      // 0..1 -> 64-col slice

  const int z = blockIdx.z;
  const __nv_bfloat16* A; const __nv_bfloat16* W; float* C; float* sumP; float* sqP;
  int N, K;
  if(mode == 0){
    A = d_featb; K = IN0; N = D1;
    W = w0 + (size_t)z*K*N;
    C = d_h0 + (size_t)z*NB*N;
    sumP = d_sum0 + z*N; sqP = d_sq0 + z*N;
  } else {
    int t = z >> 3, e = expert_of(z);
    A = d_fea1b + (size_t)t*NB*D1; K = D1; N = D2;
    W = w1 + (size_t)e*K*N;
    C = d_h1 + (size_t)z*NB*N;
    sumP = d_sum1 + z*N; sqP = d_sq1 + z*N;
  }
  const int NK = K / BKb;
  const int m0 = blockIdx.y * BM;
  const int n0 = blockIdx.x * BN;

  const __nv_bfloat16* Abase = A + (size_t)m0 * K;
  const __nv_bfloat16* Bbase = W + n0;

  auto load_stage = [&](int kc, int buf){
    const __nv_bfloat16* gA = Abase + (size_t)kc * BKb;
    const __nv_bfloat16* gB = Bbase + (size_t)kc * BKb * N;
    uint32_t sA = sb + buf * STG_B;
    uint32_t sB = sA + A_STG_B;
    #pragma unroll
    for(int it = 0; it < 8; ++it){                   // A: 128 rows x 8 chunks
      int idx = it*128 + tid;
      int r = idx >> 3, q = idx & 7;
      cp16(sA + (uint32_t)(r*A_LDb + q*8)*2, gA + (size_t)r*K + q*8);
    }
    #pragma unroll
    for(int it = 0; it < 8; ++it){                   // B: 64 rows x 16 chunks
      int idx = it*128 + tid;
      int r = idx >> 4, q = idx & 15;
      cp16(sB + (uint32_t)(r*B_LDb + q*8)*2, gB + (size_t)r*N + q*8);
    }
  };

  FC acc[4][4];
  #pragma unroll
  for(int i = 0; i < 4; ++i)
    #pragma unroll
    for(int j = 0; j < 4; ++j) wmma::fill_fragment(acc[i][j], 0.f);

  load_stage(0, 0); CP_COMMIT();
  load_stage(1, 1); CP_COMMIT();

  for(int kc = 0; kc < NK; ++kc){
    CP_WAIT(1);               // stage kc resident
    __syncthreads();          // buffer (kc+2)%3 free for refill
    int ts = kc + 2;
    if(ts < NK) load_stage(ts, ts % S_STG);
    CP_COMMIT();
    const __nv_bfloat16* As = (const __nv_bfloat16*)(sm + (kc % S_STG) * STG_B);
    const __nv_bfloat16* Bs = (const __nv_bfloat16*)(sm + (kc % S_STG) * STG_B + A_STG_B);
    #pragma unroll
    for(int ks = 0; ks < 4; ++ks){
      FB b[4];
      #pragma unroll
      for(int jn = 0; jn < 4; ++jn)
        wmma::load_matrix_sync(b[jn], Bs + (ks*16)*B_LDb + wn*64 + jn*16, B_LDb);
      #pragma unroll
      for(int im = 0; im < 4; ++im){
        FA a;
        wmma::load_matrix_sync(a, As + (wm*64 + im*16)*A_LDb + ks*16, A_LDb);
        #pragma unroll
        for(int jn = 0; jn < 4; ++jn)
          wmma::mma_sync(acc[im][jn], a, b[jn], acc[im][jn]);
      }
    }
  }
  __syncthreads();   // pipeline smem dead; reuse for epilogue

  // ---- epilogue: frags -> smem(f32) -> coalesced gmem + fused BN stats ----
  float* shf = (float*)sm;     // 128 x 132
  #pragma unroll
  for(int im = 0; im < 4; ++im)
    #pragma unroll
    for(int jn = 0; jn < 4; ++jn)
      wmma::store_matrix_sync(shf + (wm*64 + im*16)*132 + wn*64 + jn*16,
                              acc[im][jn], 132, wmma::mem_row_major);
  __syncthreads();

  float* Crow = C + (size_t)m0*N + n0;
  #pragma unroll 4
  for(int it = 0; it < 32; ++it){
    int idx = it*128 + tid;
    int row = idx >> 5, q = (idx & 31)*4;
    float4 v = make_float4(shf[row*132+q], shf[row*132+q+1],
                           shf[row*132+q+2], shf[row*132+q+3]);
    *(float4*)(Crow + (size_t)row*N + q) = v;
  }
  {
    int col = tid;
    float s = 0.f, q = 0.f;
    #pragma unroll 8
    for(int r = 0; r < 128; ++r){
      float v = shf[r*132 + col]; s += v; q += v*v;
    }
    atomicAdd(&sumP[n0 + col], s);
    atomicAdd(&sqP[n0 + col], q);
  }
}

// f32 -> bf16 conversion (weights), float4-vectorized
__global__ void conv_bf16_kernel(const float* __restrict__ src, __nv_bfloat16* __restrict__ dst, int n4){
  int i = blockIdx.x*blockDim.x + threadIdx.x;
  if(i >= n4) return;
  float4 v = *(const float4*)(src + (size_t)i*4);
  __nv_bfloat162 lo = __floats2bfloat162_rn(v.x, v.y);
  __nv_bfloat162 hi = __floats2bfloat162_rn(v.z, v.w);
  uint2 pk; pk.x = *(unsigned*)&lo; pk.y = *(unsigned*)&hi;
  *(uint2*)(dst + (size_t)i*4) = pk;
}

// ---------------- small kernels ----------------
__global__ void zero_stats_kernel(){
  int i = blockIdx.x*blockDim.x + threadIdx.x;
  if(i < 12*D1){ d_sum0[i]=0.f; d_sq0[i]=0.f; }
  if(i < 16*D2){ d_sum1[i]=0.f; d_sq1[i]=0.f; }
  if(i < 2*128){ d_sumT0[i]=0.f; d_sqT0[i]=0.f; }
  if(i < 2*64 ){ d_sumT1[i]=0.f; d_sqT1[i]=0.f; }
}

// float4 gather: 1 thread = 4 embedding elems; writes f32 + packed bf16
__global__ void gather_kernel(const int* __restrict__ x, const float* __restrict__ emb){
  int idx = blockIdx.x*blockDim.x + threadIdx.x;   // NB*NF*16
  int q = idx & 15;
  int f = (idx >> 4) % NF;
  int b = idx / (16*NF);
  int v = x[b*NF + f];
  float4 val = *(const float4*)(emb + ((size_t)f*NVOC + (size_t)v)*NE + q*4);
  *(float4*)(d_feat + (size_t)b*IN0 + f*NE + q*4) = val;
  __nv_bfloat162 lo = __floats2bfloat162_rn(val.x, val.y);
  __nv_bfloat162 hi = __floats2bfloat162_rn(val.z, val.w);
  uint2 pk; pk.x = *(unsigned*)&lo; pk.y = *(unsigned*)&hi;
  *(uint2*)(d_featb + (size_t)b*IN0 + f*NE + q*4) = pk;
}

__device__ __forceinline__ void warp_reduce16(float* acc){
  #pragma unroll
  for(int off=16; off; off>>=1)
    #pragma unroll
    for(int j=0;j<16;j++) acc[j] += __shfl_xor_sync(0xffffffffu, acc[j], off);
}
__device__ __forceinline__ void softmax8(const float* l, float* o){
  float m = l[0];
  #pragma unroll
  for(int j=1;j<8;j++) m = fmaxf(m, l[j]);
  float s = 0.f, e[8];
  #pragma unroll
  for(int j=0;j<8;j++){ e[j] = expf(l[j]-m); s += e[j]; }
  float inv = 1.f/s;
  #pragma unroll
  for(int j=0;j<8;j++) o[j] = e[j]*inv;
}

__global__ void gate0_kernel(const float* __restrict__ gw, const float* __restrict__ gb){
  int w = (blockIdx.x*blockDim.x + threadIdx.x) >> 5;
  int lane = threadIdx.x & 31;
  if(w >= NB) return;
  const float* frow = d_feat + (size_t)w*IN0;
  float acc[16];
  #pragma unroll
  for(int j=0;j<16;j++) acc[j]=0.f;
  for(int k=lane;k<IN0;k+=32){
    float fv = frow[k];
    const float* g0 = gw + k*8;
    const float* g1 = gw + IN0*8 + k*8;
    #pragma unroll
    for(int j=0;j<8;j++){ acc[j] += fv*g0[j]; acc[8+j] += fv*g1[j]; }
  }
  warp_reduce16(acc);
  if(lane==0){
    float l[8], o[8];
    #pragma unroll
    for(int t=0;t<2;t++){
      #pragma unroll
      for(int j=0;j<8;j++) l[j] = acc[t*8+j] + gb[t*8+j];
      softmax8(l,o);
      #pragma unroll
      for(int j=0;j<8;j++) d_gate0[(size_t)w*16 + t*8 + j] = o[j];
    }
  }
}

__global__ void gate1_kernel(const float* __restrict__ gw, const float* __restrict__ gb){
  int w = (blockIdx.x*blockDim.x + threadIdx.x) >> 5;
  int lane = threadIdx.x & 31;
  if(w >= NB) return;
  const float* f0 = d_fea1 + (size_t)w*D1;
  const float* f1 = d_fea1 + (size_t)NB*D1 + (size_t)w*D1;
  float acc[16];
  #pragma unroll
  for(int j=0;j<16;j++) acc[j]=0.f;
  for(int k=lane;k<D1;k+=32){
    float v0 = f0[k], v1 = f1[k];
    const float* g0 = gw + k*8;
    const float* g1 = gw + D1*8 + k*8;
    #pragma unroll
    for(int j=0;j<8;j++){ acc[j] += v0*g0[j]; acc[8+j] += v1*g1[j]; }
  }
  warp_reduce16(acc);
  if(lane==0){
    float l[8], o[8];
    #pragma unroll
    for(int t=0;t<2;t++){
      #pragma unroll
      for(int j=0;j<8;j++) l[j] = acc[t*8+j] + gb[t*8+j];
      softmax8(l,o);
      #pragma unroll
      for(int j=0;j<8;j++) d_gate1[(size_t)w*16 + t*8 + j] = o[j];
    }
  }
}

// SIMT SGEMM for the small tower layers: mode 2 / mode 3 (fused stats).
__global__ void __launch_bounds__(256,2) sgemm_kernel(int mode, const float* __restrict__ w_base){
  __shared__ float sh[2048];
  float* As = sh;
  float* Bs = sh + 1024;

  const int z = blockIdx.z;
  const float* A; const float* W; float* C; float* sumP; float* sqP;
  int N, K;
  if(mode==2){
    A=d_fea2 + (size_t)z*NB*D2; K=D2; N=128;
    W=w_base + (size_t)z*K*N; C=d_t1raw + (size_t)z*NB*N;
    sumP=d_sumT0 + z*N; sqP=d_sqT0 + z*N;
  } else {
    A=d_t1 + (size_t)z*NB*128; K=128; N=64;
    W=w_base + (size_t)z*K*N; C=d_t2raw + (size_t)z*NB*N;
    sumP=d_sumT1 + z*N; sqP=d_sqT1 + z*N;
  }

  const int tid = threadIdx.x;
  const int tx = tid & 15, ty = tid >> 4;
  const int m0 = blockIdx.y*128, n0 = blockIdx.x*128;
  const int arow = tid >> 1, acol = (tid & 1)*4;
  const int brow = tid >> 5, bcol = (tid & 31)*4;

  float acc[8][8];
  #pragma unroll
  for(int i=0;i<8;i++)
    #pragma unroll
    for(int j=0;j<8;j++) acc[i][j]=0.f;

  const float* Aptr = A + (size_t)(m0+arow)*K + acol;
  const bool bload = (n0 + bcol) < N;

  for(int k0=0; k0<K; k0+=8){
    float4 av = *(const float4*)(Aptr + k0);
    As[(acol+0)*128 + arow] = av.x;
    As[(acol+1)*128 + arow] = av.y;
    As[(acol+2)*128 + arow] = av.z;
    As[(acol+3)*128 + arow] = av.w;
    float4 bv = bload ? *(const float4*)(W + (size_t)(k0+brow)*N + n0 + bcol)
                      : make_float4(0.f,0.f,0.f,0.f);
    *(float4*)(Bs + brow*128 + bcol) = bv;
    __syncthreads();
    #pragma unroll
    for(int kk=0;kk<8;kk++){
      float a[8], bb[8];
      *(float4*)(a)    = *(float4*)(As + kk*128 + ty*8);
      *(float4*)(a+4)  = *(float4*)(As + kk*128 + ty*8 + 4);
      *(float4*)(bb)   = *(float4*)(Bs + kk*128 + tx*8);
      *(float4*)(bb+4) = *(float4*)(Bs + kk*128 + tx*8 + 4);
      #pragma unroll
      for(int i=0;i<8;i++)
        #pragma unroll
        for(int j=0;j<8;j++) acc[i][j] += a[i]*bb[j];
    }
    __syncthreads();
  }

  float s1[8], s2[8];
  #pragma unroll
  for(int j=0;j<8;j++){ s1[j]=0.f; s2[j]=0.f; }
  const bool wok = (n0 + tx*8) < N;
  #pragma unroll
  for(int i=0;i<8;i++){
    int m = m0 + ty*8 + i;
    #pragma unroll
    for(int j=0;j<8;j++){ float v = acc[i][j]; s1[j]+=v; s2[j]+=v*v; }
    if(wok){
      *(float4*)(C + (size_t)m*N + n0 + tx*8)     = *(float4*)&acc[i][0];
      *(float4*)(C + (size_t)m*N + n0 + tx*8 + 4) = *(float4*)&acc[i][4];
    }
  }
  __syncthreads();
  #pragma unroll
  for(int j=0;j<8;j++) sh[ty*128 + tx*8 + j] = s1[j];
  __syncthreads();
  if(tid < 128 && (n0 + tid) < N){
    float t = 0.f;
    #pragma unroll
    for(int r=0;r<16;r++) t += sh[r*128 + tid];
    atomicAdd(&sumP[n0 + tid], t);
  }
  __syncthreads();
  #pragma unroll
  for(int j=0;j<8;j++) sh[ty*128 + tx*8 + j] = s2[j];
  __syncthreads();
  if(tid < 128 && (n0 + tid) < N){
    float t = 0.f;
    #pragma unroll
    for(int r=0;r<16;r++) t += sh[r*128 + tid];
    atomicAdd(&sqP[n0 + tid], t);
  }
}

__global__ void finalize_kernel(int mode, const float* __restrict__ g, const float* __restrict__ bt){
  int i = blockIdx.x*blockDim.x + threadIdx.x;
  const float* sum; const float* sq; float* a; float* c; int N, NZ;
  if(mode==0){ sum=d_sum0; sq=d_sq0; a=d_a0; c=d_c0; N=D1; NZ=12; }
  else if(mode==1){ sum=d_sum1; sq=d_sq1; a=d_a1; c=d_c1; N=D2; NZ=16; }
  else if(mode==2){ sum=d_sumT0; sq=d_sqT0; a=d_aT0; c=d_cT0; N=128; NZ=2; }
  else { sum=d_sumT1; sq=d_sqT1; a=d_aT1; c=d_cT1; N=64; NZ=2; }
  if(i >= NZ*N) return;
  int z = i / N, o = i - z*N;
  int gz = (mode==1) ? expert_of(z) : z;
  float mu  = sum[i] * (1.f/NB);
  float var = sq[i] * (1.f/NB) - mu*mu;
  float aa  = g[gz*N+o] * rsqrtf(var + 1e-5f);
  a[i] = aa;
  c[i] = bt[gz*N+o] - mu*aa;
}

// float4 combine: BN+relu per expert, gate-weighted sums, writes f32 + bf16
__global__ void combine0_kernel(){
  int idx = blockIdx.x*blockDim.x + threadIdx.x;   // NB*128
  int o4 = (idx & 127)*4;
  size_t b = (size_t)(idx >> 7);
  const float* g = d_gate0 + b*16;
  float4 acc0 = make_float4(0,0,0,0), acc1 = make_float4(0,0,0,0);
  #pragma unroll
  for(int e=0;e<12;e++){
    float4 h = *(const float4*)(d_h0 + ((size_t)e*NB + b)*D1 + o4);
    float4 a = *(const float4*)(d_a0 + e*D1 + o4);
    float4 c = *(const float4*)(d_c0 + e*D1 + o4);
    float4 y;
    y.x = fmaxf(h.x*a.x + c.x, 0.f);
    y.y = fmaxf(h.y*a.y + c.y, 0.f);
    y.z = fmaxf(h.z*a.z + c.z, 0.f);
    y.w = fmaxf(h.w*a.w + c.w, 0.f);
    float g0 = (e < 4) ? g[e] : ((e >= 8) ? g[e-4] : 0.f);
    float g1 = (e >= 4) ? g[8 + e - 4] : 0.f;
    acc0.x += g0*y.x; acc0.y += g0*y.y; acc0.z += g0*y.z; acc0.w += g0*y.w;
    acc1.x += g1*y.x; acc1.y += g1*y.y; acc1.z += g1*y.z; acc1.w += g1*y.w;
  }
  *(float4*)(d_fea1 + b*D1 + o4) = acc0;
  *(float4*)(d_fea1 + (size_t)NB*D1 + b*D1 + o4) = acc1;
  __nv_bfloat162 l0 = __floats2bfloat162_rn(acc0.x, acc0.y);
  __nv_bfloat162 h0 = __floats2bfloat162_rn(acc0.z, acc0.w);
  uint2 p0; p0.x = *(unsigned*)&l0; p0.y = *(unsigned*)&h0;
  *(uint2*)(d_fea1b + b*D1 + o4) = p0;
  __nv_bfloat162 l1 = __floats2bfloat162_rn(acc1.x, acc1.y);
  __nv_bfloat162 h1 = __floats2bfloat162_rn(acc1.z, acc1.w);
  uint2 p1; p1.x = *(unsigned*)&l1; p1.y = *(unsigned*)&h1;
  *(uint2*)(d_fea1b + (size_t)NB*D1 + b*D1 + o4) = p1;
}

__global__ void combine1_kernel(){
  int idx = blockIdx.x*blockDim.x + threadIdx.x;   // NB*64
  int o4 = (idx & 63)*4;
  size_t b = (size_t)(idx >> 6);
  const float* g = d_gate1 + b*16;
  float4 acc0 = make_float4(0,0,0,0), acc1 = make_float4(0,0,0,0);
  #pragma unroll
  for(int s=0;s<16;s++){
    float4 h = *(const float4*)(d_h1 + ((size_t)s*NB + b)*D2 + o4);
    float4 a = *(const float4*)(d_a1 + s*D2 + o4);
    float4 c = *(const float4*)(d_c1 + s*D2 + o4);
    float4 y;
    y.x = fmaxf(h.x*a.x + c.x, 0.f);
    y.y = fmaxf(h.y*a.y + c.y, 0.f);
    y.z = fmaxf(h.z*a.z + c.z, 0.f);
    y.w = fmaxf(h.w*a.w + c.w, 0.f);
    float gv = g[s];
    if(s < 8){ acc0.x += gv*y.x; acc0.y += gv*y.y; acc0.z += gv*y.z; acc0.w += gv*y.w; }
    else     { acc1.x += gv*y.x; acc1.y += gv*y.y; acc1.z += gv*y.z; acc1.w += gv*y.w; }
  }
  *(float4*)(d_fea2 + b*D2 + o4) = acc0;
  *(float4*)(d_fea2 + (size_t)NB*D2 + b*D2 + o4) = acc1;
}

__global__ void normrelu_kernel(int mode){
  int i = blockIdx.x*blockDim.x + threadIdx.x;
  if(mode==0){
    if(i >= 2*NB*128) return;
    int o = i & 127; int t = i / (NB*128);
    d_t1[i] = fmaxf(d_t1raw[i]*d_aT0[t*128+o] + d_cT0[t*128+o], 0.f);
  } else {
    if(i >= 2*NB*64) return;
    int o = i & 63; int t = i / (NB*64);
    d_t2[i] = fmaxf(d_t2raw[i]*d_aT1[t*64+o] + d_cT1[t*64+o], 0.f);
  }
}

__global__ void final_kernel(const float* __restrict__ tow, const float* __restrict__ tob,
                             float* __restrict__ out){
  int w = (blockIdx.x*blockDim.x + threadIdx.x) >> 5;
  int lane = threadIdx.x & 31;
  if(w >= NB) return;
  size_t b = (size_t)w;
  float s0 = d_t2[b*64 + lane]*tow[lane] + d_t2[b*64 + lane + 32]*tow[lane + 32];
  float s1 = d_t2[(size_t)NB*64 + b*64 + lane]*tow[64 + lane]
           + d_t2[(size_t)NB*64 + b*64 + lane + 32]*tow[64 + lane + 32];
  #pragma unroll
  for(int off=16; off; off>>=1){
    s0 += __shfl_xor_sync(0xffffffffu, s0, off);
    s1 += __shfl_xor_sync(0xffffffffu, s1, off);
  }
  if(lane==0){
    out[b]      = 1.f/(1.f + expf(-(s0 + tob[0])));
    out[NB + b] = 1.f/(1.f + expf(-(s1 + tob[1])));
  }
}

// ---------------- host launcher ----------------
extern "C" void kernel_launch(void* const* d_in, const int* in_sizes, int n_in,
                              void* d_out, int out_size){
  const int*   x    = (const int*)  d_in[0];
  const float* emb  = (const float*)d_in[1];
  const float* ew0  = (const float*)d_in[2];
  const float* eg0  = (const float*)d_in[4];
  const float* ebt0 = (const float*)d_in[5];
  const float* gw0  = (const float*)d_in[6];
  const float* gb0  = (const float*)d_in[7];
  const float* ew1  = (const float*)d_in[10];
  const float* eg1  = (const float*)d_in[12];
  const float* ebt1 = (const float*)d_in[13];
  const float* gw1  = (const float*)d_in[14];
  const float* gb1  = (const float*)d_in[15];
  const float* tw0  = (const float*)d_in[18];
  const float* tg0  = (const float*)d_in[20];
  const float* tbt0 = (const float*)d_in[21];
  const float* tw1  = (const float*)d_in[22];
  const float* tg1  = (const float*)d_in[24];
  const float* tbt1 = (const float*)d_in[25];
  const float* tow  = (const float*)d_in[26];
  const float* tob  = (const float*)d_in[27];
  float* out = (float*)d_out;

  static bool attr_set = false;
  if(!attr_set){
    cudaFuncSetAttribute(bf16_gemm_kernel, cudaFuncAttributeMaxDynamicSharedMemorySize, SMEM_GB);
    attr_set = true;
  }

  __nv_bfloat16* w0b; cudaGetSymbolAddress((void**)&w0b, d_w0b);
  __nv_bfloat16* w1b; cudaGetSymbolAddress((void**)&w1b, d_w1b);

  zero_stats_kernel<<<(12*D1 + 255)/256, 256>>>();
  conv_bf16_kernel<<<(12*IN0*D1/4 + 255)/256, 256>>>(ew0, w0b, 12*IN0*D1/4);
  conv_bf16_kernel<<<(12*D1*D2/4 + 255)/256, 256>>>(ew1, w1b, 12*D1*D2/4);
  gather_kernel<<<(NB*NF*16)/256, 256>>>(x, emb);
  gate0_kernel<<<(NB*32)/256, 256>>>(gw0, gb0);

  bf16_gemm_kernel<<<dim3(D1/BN, NB/BM, 12), 128, SMEM_GB>>>(0, w0b, w1b);
  finalize_kernel<<<(12*D1 + 255)/256, 256>>>(0, eg0, ebt0);
  combine0_kernel<<<(NB*128)/256, 256>>>();

  gate1_kernel<<<(NB*32)/256, 256>>>(gw1, gb1);
  bf16_gemm_kernel<<<dim3(D2/BN, NB/BM, 16), 128, SMEM_GB>>>(1, w0b, w1b);
  finalize_kernel<<<(16*D2 + 255)/256, 256>>>(1, eg1, ebt1);
  combine1_kernel<<<(NB*64)/256, 256>>>();

  sgemm_kernel<<<dim3(1, NB/128, 2), 256>>>(2, tw0);
  finalize_kernel<<<1, 256>>>(2, tg0, tbt0);
  normrelu_kernel<<<(2*NB*128)/256, 256>>>(0);

  sgemm_kernel<<<dim3(1, NB/128, 2), 256>>>(3, tw1);
  finalize_kernel<<<1, 256>>>(3, tg1, tbt1);
  normrelu_kernel<<<(2*NB*64)/256, 256>>>(1);

  final_kernel<<<(NB*32)/256, 256>>>(tow, tob, out);
}